// round 11
// baseline (speedup 1.0000x reference)
#include <cuda_runtime.h>
#include <cuda_fp16.h>
#include <cstdint>

#define FIN 100
#define HD  64
#define NMAX 100000
#define EMAX 3200000
#define NBMAX 128

// ---------------- scratch (device globals) -----------------------------------
__device__ __half g_hA16[NMAX * HD];
__device__ __half g_hB16[NMAX * HD];
__device__ __half g_xlo16[NMAX * HD];
__device__ __half g_xhi16[NMAX * HD];
__device__ float  g_Wemb[2 * HD * HD];
__device__ float  g_W4[2 * HD * HD];
__device__ float  g_b4[HD];
__device__ int    g_cnt[NMAX];
__device__ int    g_rowstart[NMAX + 1];
__device__ int    g_cursor[NMAX];
__device__ int    g_bsum[NBMAX];
__device__ int    g_boff[NBMAX];
__device__ int2   g_edge[EMAX];

// ---------------- helpers ------------------------------------------------------
__device__ __forceinline__ uint32_t f2h2(float lo, float hi) {
    __half2 h = __floats2half2_rn(lo, hi);
    return *reinterpret_cast<uint32_t*>(&h);
}

__device__ __forceinline__ void mma16816(float c[4], const uint32_t a[4],
                                         const uint32_t b[2]) {
    asm volatile(
        "mma.sync.aligned.m16n8k16.row.col.f32.f16.f16.f32 "
        "{%0,%1,%2,%3}, {%4,%5,%6,%7}, {%8,%9}, {%0,%1,%2,%3};\n"
        : "+f"(c[0]), "+f"(c[1]), "+f"(c[2]), "+f"(c[3])
        : "r"(a[0]), "r"(a[1]), "r"(a[2]), "r"(a[3]), "r"(b[0]), "r"(b[1]));
}

// ---------------- K1: convert_x | pad | hist (block-range roles) ---------------
__global__ void prep_kernel(const float* __restrict__ x,
                            const float* __restrict__ embW,
                            const float* __restrict__ Wl4,
                            const float* __restrict__ bl4,
                            const float* __restrict__ Wr4,
                            const int* __restrict__ ei,
                            int n, int e, int CB) {
    int bid = blockIdx.x;
    if (bid < CB) {
        int base = (bid * 256 + threadIdx.x) * 4;
        if (base >= n * HD) return;
        int node = base >> 6;
        int c    = base & 63;
        const float* xr = x + (size_t)node * FIN;
        float4 lo = *(const float4*)(xr + c);
        uint2 lo2 = make_uint2(f2h2(lo.x, lo.y), f2h2(lo.z, lo.w));
        *(uint2*)(g_xlo16 + base) = lo2;
        float4 hi = make_float4(0.f, 0.f, 0.f, 0.f);
        if (c < FIN - HD) hi = *(const float4*)(xr + HD + c);
        uint2 hi2 = make_uint2(f2h2(hi.x, hi.y), f2h2(hi.z, hi.w));
        *(uint2*)(g_xhi16 + base) = hi2;
    } else if (bid < CB + 32) {
        int tid = (bid - CB) * 256 + threadIdx.x;
        if (tid < 2 * HD * HD) {
            int k = tid >> 6, c = tid & 63;
            g_Wemb[tid] = (k < FIN) ? embW[k * HD + c] : 0.0f;
        }
        if (tid < HD * HD) {
            int k = tid >> 6, c = tid & 63;
            g_W4[tid]           = (c < 18) ? Wl4[k * 18 + c] : 0.0f;
            g_W4[HD * HD + tid] = (c < 18) ? Wr4[k * 18 + c] : 0.0f;
        }
        if (tid < HD) g_b4[tid] = (tid < 18) ? bl4[tid] : 0.0f;
    } else {
        int base = ((bid - CB - 32) * 256 + threadIdx.x) * 4;
#pragma unroll
        for (int j = 0; j < 4; ++j) {
            int i = base + j;
            if (i < e) {
                int dst = ei[e + i];
                dst = min(max(dst, 0), n - 1);
                atomicAdd(&g_cnt[dst], 1);
            }
        }
    }
}

// ---------------- scan phases ---------------------------------------------------
__global__ void block_sum_kernel(int n) {
    __shared__ int sw[8];
    int base = blockIdx.x * 1024;
    int tid  = threadIdx.x;
    int s = 0;
#pragma unroll
    for (int j = 0; j < 4; ++j) {
        int i = base + j * 256 + tid;
        if (i < n) s += g_cnt[i];
    }
#pragma unroll
    for (int o = 16; o; o >>= 1) s += __shfl_xor_sync(~0u, s, o);
    if ((tid & 31) == 0) sw[tid >> 5] = s;
    __syncthreads();
    if (tid == 0) {
        int t = 0;
#pragma unroll
        for (int w = 0; w < 8; ++w) t += sw[w];
        g_bsum[blockIdx.x] = t;
    }
}

__global__ void scan_bsum_kernel(int nb, int n) {
    __shared__ int sw[4];
    int tid  = threadIdx.x;
    int lane = tid & 31;
    int warp = tid >> 5;
    int v = (tid < nb) ? g_bsum[tid] : 0;
    int x = v;
#pragma unroll
    for (int o = 1; o < 32; o <<= 1) {
        int y = __shfl_up_sync(~0u, x, o);
        if (lane >= o) x += y;
    }
    if (lane == 31) sw[warp] = x;
    __syncthreads();
    if (tid < 4) {
        int y = sw[tid];
#pragma unroll
        for (int o = 1; o < 4; o <<= 1) {
            int z = __shfl_up_sync(0xF, y, o);
            if (tid >= o) y += z;
        }
        sw[tid] = y;
    }
    __syncthreads();
    int incl = x + (warp > 0 ? sw[warp - 1] : 0);
    if (tid < nb) g_boff[tid] = incl - v;
    if (tid == 127) g_rowstart[n] = incl;
}

__global__ void write_rowstart_kernel(int n) {
    __shared__ int sw[8];
    int base = blockIdx.x * 1024;
    int tid  = threadIdx.x;
    int lane = tid & 31;
    int warp = tid >> 5;
    int i0 = base + tid * 4;
    int c[4];
    int ts = 0;
#pragma unroll
    for (int j = 0; j < 4; ++j) {
        int i = i0 + j;
        c[j] = (i < n) ? g_cnt[i] : 0;
        ts += c[j];
    }
    int x = ts;
#pragma unroll
    for (int o = 1; o < 32; o <<= 1) {
        int y = __shfl_up_sync(~0u, x, o);
        if (lane >= o) x += y;
    }
    if (lane == 31) sw[warp] = x;
    __syncthreads();
    if (tid < 8) {
        int y = sw[tid];
#pragma unroll
        for (int o = 1; o < 8; o <<= 1) {
            int z = __shfl_up_sync(0xFF, y, o);
            if (tid >= o) y += z;
        }
        sw[tid] = y;
    }
    __syncthreads();
    int run = g_boff[blockIdx.x] + (x - ts) + (warp > 0 ? sw[warp - 1] : 0);
#pragma unroll
    for (int j = 0; j < 4; ++j) {
        int i = i0 + j;
        if (i < n) {
            g_rowstart[i] = run;
            g_cursor[i]   = run;
        }
        run += c[j];
    }
}

// ---------------- K2: embed transform | fill (block-range roles) ---------------
__global__ void __launch_bounds__(256)
embed_fill_kernel(const int* __restrict__ ei, const float* __restrict__ w,
                  const float* __restrict__ Wl, const float* __restrict__ bl,
                  const float* __restrict__ Wr,
                  __half* __restrict__ out16, int n, int e, int TB) {
    int bid = blockIdx.x;
    if (bid >= TB) {   // ---- fill role ----
        int base = ((bid - TB) * 256 + threadIdx.x) * 4;
#pragma unroll
        for (int j = 0; j < 4; ++j) {
            int i = base + j;
            if (i < e) {
                int dst = ei[e + i];
                int src = ei[i];
                dst = min(max(dst, 0), n - 1);
                src = min(max(src, 0), n - 1);
                int pos = atomicAdd(&g_cursor[dst], 1);
                pos = min(max(pos, 0), EMAX - 1);
                g_edge[pos] = make_int2(src, __float_as_int(w[i]));
            }
        }
        return;
    }
    // ---- embed transform role ----
    int warp  = threadIdx.x >> 5;
    int lane  = threadIdx.x & 31;
    int g     = lane >> 2;
    int tig   = lane & 3;
    int sub   = warp & 3;
    int grp   = warp >> 2;
    int nbase = sub * 16;

    uint32_t Bl[4][2][2], Br[4][2][2];
#pragma unroll
    for (int ks = 0; ks < 4; ++ks)
#pragma unroll
        for (int nst = 0; nst < 2; ++nst) {
            int ncol = nbase + nst * 8 + g;
#pragma unroll
            for (int rr = 0; rr < 2; ++rr) {
                int k = ks * 16 + 2 * tig + rr * 8;
                Bl[ks][nst][rr] = f2h2(Wl[k * HD + ncol], Wl[(k + 1) * HD + ncol]);
                Br[ks][nst][rr] = f2h2(Wr[k * HD + ncol], Wr[(k + 1) * HD + ncol]);
            }
        }
    float bb[2][2];
#pragma unroll
    for (int nst = 0; nst < 2; ++nst) {
        bb[nst][0] = bl[nbase + nst * 8 + 2 * tig];
        bb[nst][1] = bl[nbase + nst * 8 + 2 * tig + 1];
    }

    const uint32_t* m2 = (const uint32_t*)g_xlo16;
    const uint32_t* r2 = (const uint32_t*)g_xhi16;
    int ntiles = (n + 15) >> 4;
    int npairs = (ntiles + 1) >> 1;

    for (int pr = bid; pr < npairs; pr += TB) {
        int tile = pr * 2 + grp;
        if (tile >= ntiles) continue;
        int row1 = tile * 16 + g;
        int row2 = row1 + 8;
        int rr1 = min(row1, n - 1);
        int rr2 = min(row2, n - 1);

        float c[2][4];
#pragma unroll
        for (int nst = 0; nst < 2; ++nst) {
            c[nst][0] = bb[nst][0]; c[nst][1] = bb[nst][1];
            c[nst][2] = bb[nst][0]; c[nst][3] = bb[nst][1];
        }
#pragma unroll
        for (int ks = 0; ks < 4; ++ks) {
            uint32_t a[4];
            a[0] = m2[rr1 * 32 + ks * 8 + tig];
            a[1] = m2[rr2 * 32 + ks * 8 + tig];
            a[2] = m2[rr1 * 32 + ks * 8 + tig + 4];
            a[3] = m2[rr2 * 32 + ks * 8 + tig + 4];
            mma16816(c[0], a, Bl[ks][0]);
            mma16816(c[1], a, Bl[ks][1]);
        }
#pragma unroll
        for (int ks = 0; ks < 4; ++ks) {
            uint32_t a[4];
            a[0] = r2[rr1 * 32 + ks * 8 + tig];
            a[1] = r2[rr2 * 32 + ks * 8 + tig];
            a[2] = r2[rr1 * 32 + ks * 8 + tig + 4];
            a[3] = r2[rr2 * 32 + ks * 8 + tig + 4];
            mma16816(c[0], a, Br[ks][0]);
            mma16816(c[1], a, Br[ks][1]);
        }
#pragma unroll
        for (int nst = 0; nst < 2; ++nst) {
            int col = nbase + nst * 8 + 2 * tig;
            float o0 = fmaxf(c[nst][0], 0.0f), o1 = fmaxf(c[nst][1], 0.0f);
            float p0 = fmaxf(c[nst][2], 0.0f), p1 = fmaxf(c[nst][3], 0.0f);
            if (row1 < n)
                ((__half2*)out16)[row1 * 32 + (col >> 1)] = __floats2half2_rn(o0, o1);
            if (row2 < n)
                ((__half2*)out16)[row2 * 32 + (col >> 1)] = __floats2half2_rn(p0, p1);
        }
    }
}

// ---------------- fused SAGE layer v2 ------------------------------------------
// 256 thr / 8 warps; tile = 16 nodes; warp w gathers nodes (tile*16+w, +8) at
// full warp-per-node parallelism; then all 8 warps transform (n-slice 8 cols).
// 4 blocks/SM resident -> other blocks' gathers hide this block's transform.
template <bool USE_W, bool RELU, bool W16, bool WF32>
__global__ void __launch_bounds__(256, 4)
sage_layer_kernel(const __half* __restrict__ hin16,
                  const float* __restrict__ Wl,
                  const float* __restrict__ bl,
                  const float* __restrict__ Wr,
                  float* __restrict__ outf, int ostride, int ocols,
                  __half* __restrict__ out16, int n) {
    __shared__ uint32_t smean[16][36];   // stride 36: conflict-free A access
    __shared__ int2     sedge[8][32];
    __shared__ __align__(16) float ssq[16][8];

    int warp = threadIdx.x >> 5;
    int lane = threadIdx.x & 31;
    int g    = lane >> 2;
    int tig  = lane & 3;
    int nbase = warp * 8;               // warp's 8 output cols

    // --- B fragments (warp's 8 cols) + bias, once per block ---
    uint32_t Bl[4][2], Br[4][2];
#pragma unroll
    for (int ks = 0; ks < 4; ++ks) {
        int ncol = nbase + g;
#pragma unroll
        for (int rr = 0; rr < 2; ++rr) {
            int k = ks * 16 + 2 * tig + rr * 8;
            Bl[ks][rr] = f2h2(Wl[k * HD + ncol], Wl[(k + 1) * HD + ncol]);
            Br[ks][rr] = f2h2(Wr[k * HD + ncol], Wr[(k + 1) * HD + ncol]);
        }
    }
    float bb0 = bl[nbase + 2 * tig];
    float bb1 = bl[nbase + 2 * tig + 1];

    const uint32_t* h2u = (const uint32_t*)hin16;
    int ntiles = (n + 15) >> 4;

    for (int tile = blockIdx.x; tile < ntiles; tile += gridDim.x) {
        // ---- gather: warp w -> local rows w and w+8 (1 node per warp pass) ----
#pragma unroll
        for (int r = 0; r < 2; ++r) {
            int lr   = warp + r * 8;
            int node = tile * 16 + lr;
            int nc   = min(node, n - 1);
            int start = g_rowstart[nc];
            int end   = g_rowstart[nc + 1];

            float a0 = 0.0f, a1 = 0.0f;
            for (int i0 = start; i0 < end; i0 += 32) {
                int mm = min(32, end - i0);
                int2 eg = make_int2(0, 0);
                if (lane < mm) eg = g_edge[i0 + lane];
                sedge[warp][lane] = eg;
                __syncwarp();
                int m8 = (mm + 7) & ~7;
                for (int j0 = 0; j0 < m8; j0 += 8) {
                    int2 e[8]; uint32_t v[8];
#pragma unroll
                    for (int jj = 0; jj < 8; ++jj) e[jj] = sedge[warp][j0 + jj];
#pragma unroll
                    for (int jj = 0; jj < 8; ++jj) v[jj] = h2u[e[jj].x * 32 + lane];
#pragma unroll
                    for (int jj = 0; jj < 8; ++jj) {
                        float w = USE_W ? __int_as_float(e[jj].y)
                                        : ((j0 + jj < mm) ? 1.0f : 0.0f);
                        __half2 hv = *reinterpret_cast<__half2*>(&v[jj]);
                        float2 f = __half22float2(hv);
                        a0 = fmaf(w, f.x, a0);
                        a1 = fmaf(w, f.y, a1);
                    }
                }
                __syncwarp();
            }
            float invd = 1.0f / fmaxf((float)(end - start), 1.0f);
            smean[lr][lane] = f2h2(a0 * invd, a1 * invd);
        }
        __syncthreads();

        // ---- transform: 16 rows x (warp's 8 cols) ----
        int row1 = tile * 16 + g;
        int row2 = row1 + 8;
        int rr1 = min(row1, n - 1);
        int rr2 = min(row2, n - 1);

        float c[4] = {bb0, bb1, bb0, bb1};
#pragma unroll
        for (int ks = 0; ks < 4; ++ks) {
            uint32_t a[4];
            a[0] = smean[g][ks * 8 + tig];
            a[1] = smean[g + 8][ks * 8 + tig];
            a[2] = smean[g][ks * 8 + tig + 4];
            a[3] = smean[g + 8][ks * 8 + tig + 4];
            mma16816(c, a, Bl[ks]);
        }
#pragma unroll
        for (int ks = 0; ks < 4; ++ks) {
            uint32_t a[4];
            a[0] = h2u[rr1 * 32 + ks * 8 + tig];
            a[1] = h2u[rr2 * 32 + ks * 8 + tig];
            a[2] = h2u[rr1 * 32 + ks * 8 + tig + 4];
            a[3] = h2u[rr2 * 32 + ks * 8 + tig + 4];
            mma16816(c, a, Br[ks]);
        }

        // ---- L2 norm across all 64 cols (8 warps x 8-col partials) ----
        float s1 = c[0] * c[0] + c[1] * c[1];
        float s2 = c[2] * c[2] + c[3] * c[3];
        s1 += __shfl_xor_sync(~0u, s1, 1); s1 += __shfl_xor_sync(~0u, s1, 2);
        s2 += __shfl_xor_sync(~0u, s2, 1); s2 += __shfl_xor_sync(~0u, s2, 2);
        if (tig == 0) { ssq[g][warp] = s1; ssq[g + 8][warp] = s2; }
        __syncthreads();
        float4 q1a = *(const float4*)&ssq[g][0];
        float4 q1b = *(const float4*)&ssq[g][4];
        float4 q2a = *(const float4*)&ssq[g + 8][0];
        float4 q2b = *(const float4*)&ssq[g + 8][4];
        float inv1 = 1.0f / fmaxf(sqrtf(q1a.x + q1a.y + q1a.z + q1a.w +
                                        q1b.x + q1b.y + q1b.z + q1b.w), 1e-12f);
        float inv2 = 1.0f / fmaxf(sqrtf(q2a.x + q2a.y + q2a.z + q2a.w +
                                        q2b.x + q2b.y + q2b.z + q2b.w), 1e-12f);

        int col = nbase + 2 * tig;
        float o0 = c[0] * inv1, o1 = c[1] * inv1;
        float p0 = c[2] * inv2, p1 = c[3] * inv2;
        if (RELU) {
            o0 = fmaxf(o0, 0.0f); o1 = fmaxf(o1, 0.0f);
            p0 = fmaxf(p0, 0.0f); p1 = fmaxf(p1, 0.0f);
        }
        if (W16) {
            if (row1 < n)
                ((__half2*)out16)[row1 * 32 + (col >> 1)] = __floats2half2_rn(o0, o1);
            if (row2 < n)
                ((__half2*)out16)[row2 * 32 + (col >> 1)] = __floats2half2_rn(p0, p1);
        }
        if (WF32) {
            if (row1 < n && col < ocols) {
                outf[(size_t)row1 * ostride + col] = o0;
                if (col + 1 < ocols) outf[(size_t)row1 * ostride + col + 1] = o1;
            }
            if (row2 < n && col < ocols) {
                outf[(size_t)row2 * ostride + col] = p0;
                if (col + 1 < ocols) outf[(size_t)row2 * ostride + col + 1] = p1;
            }
        }
        // next tile's post-gather __syncthreads orders smean/ssq reuse
    }
}

// ---------------- launch ---------------------------------------------------------
extern "C" void kernel_launch(void* const* d_in, const int* in_sizes, int n_in,
                              void* d_out, int out_size) {
    const float* x    = (const float*)d_in[0];
    const int*   ei   = (const int*)d_in[1];     // int32 [2, E]
    const float* ew   = (const float*)d_in[2];
    const float* embW = (const float*)d_in[3];
    const float* embB = (const float*)d_in[4];
    const float* Wl1 = (const float*)d_in[5];
    const float* bl1 = (const float*)d_in[6];
    const float* Wr1 = (const float*)d_in[7];
    const float* Wl2 = (const float*)d_in[8];
    const float* bl2 = (const float*)d_in[9];
    const float* Wr2 = (const float*)d_in[10];
    const float* Wl3 = (const float*)d_in[11];
    const float* bl3 = (const float*)d_in[12];
    const float* Wr3 = (const float*)d_in[13];
    const float* Wl4 = (const float*)d_in[14];
    const float* bl4 = (const float*)d_in[15];
    const float* Wr4 = (const float*)d_in[16];

    int n = in_sizes[0] / FIN;
    int e = in_sizes[2];

    __half *hA16, *hB16;
    float *Wemb, *W4, *b4; int* cnt;
    cudaGetSymbolAddress((void**)&hA16, g_hA16);
    cudaGetSymbolAddress((void**)&hB16, g_hB16);
    cudaGetSymbolAddress((void**)&Wemb, g_Wemb);
    cudaGetSymbolAddress((void**)&W4,   g_W4);
    cudaGetSymbolAddress((void**)&b4,   g_b4);
    cudaGetSymbolAddress((void**)&cnt,  g_cnt);

    cudaMemsetAsync(cnt, 0, (size_t)n * sizeof(int));

    // K1: convert | pad | hist
    int CB = (n * HD / 4 + 255) / 256;
    int HB = (e / 4 + 255) / 256;
    prep_kernel<<<CB + 32 + HB, 256>>>(x, embW, Wl4, bl4, Wr4, ei, n, e, CB);

    int nb = (n + 1023) / 1024;
    block_sum_kernel<<<nb, 256>>>(n);
    scan_bsum_kernel<<<1, 128>>>(nb, n);
    write_rowstart_kernel<<<nb, 256>>>(n);

    // K2: embed transform | fill
    const int TB = 1036;
    int FB = (e / 4 + 255) / 256;
    embed_fill_kernel<<<TB + FB, 256>>>(ei, ew, Wemb, embB, Wemb + HD * HD,
                                        hA16, n, e, TB);

    // fused per-layer kernels (persistent grid-stride)
    const int LG = 1184;
    sage_layer_kernel<true,  true,  true,  false><<<LG, 256>>>(
        hA16, Wl1, bl1, Wr1, nullptr, 0, 0, hB16, n);
    sage_layer_kernel<true,  true,  true,  false><<<LG, 256>>>(
        hB16, Wl2, bl2, Wr2, nullptr, 0, 0, hA16, n);
    sage_layer_kernel<true,  true,  true,  false><<<LG, 256>>>(
        hA16, Wl3, bl3, Wr3, nullptr, 0, 0, hB16, n);
    sage_layer_kernel<false, false, false, true ><<<LG, 256>>>(
        hB16, W4, b4, W4 + HD * HD, (float*)d_out, 18, 18, nullptr, n);
}

// round 12
// speedup vs baseline: 1.0172x; 1.0172x over previous
#include <cuda_runtime.h>
#include <cuda_fp16.h>
#include <cstdint>

#define FIN 100
#define HD  64
#define NMAX 100000
#define EMAX 3200000
#define NBMAX 128

// ---------------- scratch (device globals) -----------------------------------
__device__ __half g_hA16[NMAX * HD];
__device__ __half g_hB16[NMAX * HD];
__device__ __half g_mv16[NMAX * HD];
__device__ __half g_xlo16[NMAX * HD];
__device__ __half g_xhi16[NMAX * HD];
__device__ float  g_Wemb[2 * HD * HD];
__device__ float  g_W4[2 * HD * HD];
__device__ float  g_b4[HD];
__device__ int    g_cnt[NMAX];
__device__ int    g_rowstart[NMAX + 1];
__device__ int    g_cursor[NMAX];
__device__ int    g_bsum[NBMAX];
__device__ int    g_boff[NBMAX];
__device__ int2   g_edge[EMAX];

// ---------------- helpers ------------------------------------------------------
__device__ __forceinline__ uint32_t f2h2(float lo, float hi) {
    __half2 h = __floats2half2_rn(lo, hi);
    return *reinterpret_cast<uint32_t*>(&h);
}

__device__ __forceinline__ void mma16816(float c[4], const uint32_t a[4],
                                         const uint32_t b[2]) {
    asm volatile(
        "mma.sync.aligned.m16n8k16.row.col.f32.f16.f16.f32 "
        "{%0,%1,%2,%3}, {%4,%5,%6,%7}, {%8,%9}, {%0,%1,%2,%3};\n"
        : "+f"(c[0]), "+f"(c[1]), "+f"(c[2]), "+f"(c[3])
        : "r"(a[0]), "r"(a[1]), "r"(a[2]), "r"(a[3]), "r"(b[0]), "r"(b[1]));
}

// ---------------- K1: convert_x | pad | hist (block-range roles) ---------------
__global__ void prep_kernel(const float* __restrict__ x,
                            const float* __restrict__ embW,
                            const float* __restrict__ Wl4,
                            const float* __restrict__ bl4,
                            const float* __restrict__ Wr4,
                            const int* __restrict__ ei,
                            int n, int e, int CB) {
    int bid = blockIdx.x;
    if (bid < CB) {
        int base = (bid * 256 + threadIdx.x) * 4;
        if (base >= n * HD) return;
        int node = base >> 6;
        int c    = base & 63;
        const float* xr = x + (size_t)node * FIN;
        float4 lo = *(const float4*)(xr + c);
        uint2 lo2 = make_uint2(f2h2(lo.x, lo.y), f2h2(lo.z, lo.w));
        *(uint2*)(g_xlo16 + base) = lo2;
        float4 hi = make_float4(0.f, 0.f, 0.f, 0.f);
        if (c < FIN - HD) hi = *(const float4*)(xr + HD + c);
        uint2 hi2 = make_uint2(f2h2(hi.x, hi.y), f2h2(hi.z, hi.w));
        *(uint2*)(g_xhi16 + base) = hi2;
    } else if (bid < CB + 32) {
        int tid = (bid - CB) * 256 + threadIdx.x;
        if (tid < 2 * HD * HD) {
            int k = tid >> 6, c = tid & 63;
            g_Wemb[tid] = (k < FIN) ? embW[k * HD + c] : 0.0f;
        }
        if (tid < HD * HD) {
            int k = tid >> 6, c = tid & 63;
            g_W4[tid]           = (c < 18) ? Wl4[k * 18 + c] : 0.0f;
            g_W4[HD * HD + tid] = (c < 18) ? Wr4[k * 18 + c] : 0.0f;
        }
        if (tid < HD) g_b4[tid] = (tid < 18) ? bl4[tid] : 0.0f;
    } else {
        int base = ((bid - CB - 32) * 256 + threadIdx.x) * 4;
#pragma unroll
        for (int j = 0; j < 4; ++j) {
            int i = base + j;
            if (i < e) {
                int dst = ei[e + i];
                dst = min(max(dst, 0), n - 1);
                atomicAdd(&g_cnt[dst], 1);
            }
        }
    }
}

// ---------------- scan phases ---------------------------------------------------
__global__ void block_sum_kernel(int n) {
    __shared__ int sw[8];
    int base = blockIdx.x * 1024;
    int tid  = threadIdx.x;
    int s = 0;
#pragma unroll
    for (int j = 0; j < 4; ++j) {
        int i = base + j * 256 + tid;
        if (i < n) s += g_cnt[i];
    }
#pragma unroll
    for (int o = 16; o; o >>= 1) s += __shfl_xor_sync(~0u, s, o);
    if ((tid & 31) == 0) sw[tid >> 5] = s;
    __syncthreads();
    if (tid == 0) {
        int t = 0;
#pragma unroll
        for (int w = 0; w < 8; ++w) t += sw[w];
        g_bsum[blockIdx.x] = t;
    }
}

__global__ void scan_bsum_kernel(int nb, int n) {
    __shared__ int sw[4];
    int tid  = threadIdx.x;
    int lane = tid & 31;
    int warp = tid >> 5;
    int v = (tid < nb) ? g_bsum[tid] : 0;
    int x = v;
#pragma unroll
    for (int o = 1; o < 32; o <<= 1) {
        int y = __shfl_up_sync(~0u, x, o);
        if (lane >= o) x += y;
    }
    if (lane == 31) sw[warp] = x;
    __syncthreads();
    if (tid < 4) {
        int y = sw[tid];
#pragma unroll
        for (int o = 1; o < 4; o <<= 1) {
            int z = __shfl_up_sync(0xF, y, o);
            if (tid >= o) y += z;
        }
        sw[tid] = y;
    }
    __syncthreads();
    int incl = x + (warp > 0 ? sw[warp - 1] : 0);
    if (tid < nb) g_boff[tid] = incl - v;
    if (tid == 127) g_rowstart[n] = incl;
}

__global__ void write_rowstart_kernel(int n) {
    __shared__ int sw[8];
    int base = blockIdx.x * 1024;
    int tid  = threadIdx.x;
    int lane = tid & 31;
    int warp = tid >> 5;
    int i0 = base + tid * 4;
    int c[4];
    int ts = 0;
#pragma unroll
    for (int j = 0; j < 4; ++j) {
        int i = i0 + j;
        c[j] = (i < n) ? g_cnt[i] : 0;
        ts += c[j];
    }
    int x = ts;
#pragma unroll
    for (int o = 1; o < 32; o <<= 1) {
        int y = __shfl_up_sync(~0u, x, o);
        if (lane >= o) x += y;
    }
    if (lane == 31) sw[warp] = x;
    __syncthreads();
    if (tid < 8) {
        int y = sw[tid];
#pragma unroll
        for (int o = 1; o < 8; o <<= 1) {
            int z = __shfl_up_sync(0xFF, y, o);
            if (tid >= o) y += z;
        }
        sw[tid] = y;
    }
    __syncthreads();
    int run = g_boff[blockIdx.x] + (x - ts) + (warp > 0 ? sw[warp - 1] : 0);
#pragma unroll
    for (int j = 0; j < 4; ++j) {
        int i = i0 + j;
        if (i < n) {
            g_rowstart[i] = run;
            g_cursor[i]   = run;
        }
        run += c[j];
    }
}

// ---------------- K2: embed transform | fill (block-range roles) ---------------
__global__ void __launch_bounds__(256)
embed_fill_kernel(const int* __restrict__ ei, const float* __restrict__ w,
                  const float* __restrict__ Wl, const float* __restrict__ bl,
                  const float* __restrict__ Wr,
                  __half* __restrict__ out16, int n, int e, int TB) {
    int bid = blockIdx.x;
    if (bid >= TB) {   // ---- fill role ----
        int base = ((bid - TB) * 256 + threadIdx.x) * 4;
#pragma unroll
        for (int j = 0; j < 4; ++j) {
            int i = base + j;
            if (i < e) {
                int dst = ei[e + i];
                int src = ei[i];
                dst = min(max(dst, 0), n - 1);
                src = min(max(src, 0), n - 1);
                int pos = atomicAdd(&g_cursor[dst], 1);
                pos = min(max(pos, 0), EMAX - 1);
                g_edge[pos] = make_int2(src, __float_as_int(w[i]));
            }
        }
        return;
    }
    // ---- embed transform role ----
    int warp  = threadIdx.x >> 5;
    int lane  = threadIdx.x & 31;
    int g     = lane >> 2;
    int tig   = lane & 3;
    int sub   = warp & 3;
    int grp   = warp >> 2;
    int nbase = sub * 16;

    uint32_t Bl[4][2][2], Br[4][2][2];
#pragma unroll
    for (int ks = 0; ks < 4; ++ks)
#pragma unroll
        for (int nst = 0; nst < 2; ++nst) {
            int ncol = nbase + nst * 8 + g;
#pragma unroll
            for (int rr = 0; rr < 2; ++rr) {
                int k = ks * 16 + 2 * tig + rr * 8;
                Bl[ks][nst][rr] = f2h2(Wl[k * HD + ncol], Wl[(k + 1) * HD + ncol]);
                Br[ks][nst][rr] = f2h2(Wr[k * HD + ncol], Wr[(k + 1) * HD + ncol]);
            }
        }
    float bb[2][2];
#pragma unroll
    for (int nst = 0; nst < 2; ++nst) {
        bb[nst][0] = bl[nbase + nst * 8 + 2 * tig];
        bb[nst][1] = bl[nbase + nst * 8 + 2 * tig + 1];
    }

    const uint32_t* m2 = (const uint32_t*)g_xlo16;
    const uint32_t* r2 = (const uint32_t*)g_xhi16;
    int ntiles = (n + 15) >> 4;
    int npairs = (ntiles + 1) >> 1;

    for (int pr = bid; pr < npairs; pr += TB) {
        int tile = pr * 2 + grp;
        if (tile >= ntiles) continue;
        int row1 = tile * 16 + g;
        int row2 = row1 + 8;
        int rr1 = min(row1, n - 1);
        int rr2 = min(row2, n - 1);

        float c[2][4];
#pragma unroll
        for (int nst = 0; nst < 2; ++nst) {
            c[nst][0] = bb[nst][0]; c[nst][1] = bb[nst][1];
            c[nst][2] = bb[nst][0]; c[nst][3] = bb[nst][1];
        }
#pragma unroll
        for (int ks = 0; ks < 4; ++ks) {
            uint32_t a[4];
            a[0] = m2[rr1 * 32 + ks * 8 + tig];
            a[1] = m2[rr2 * 32 + ks * 8 + tig];
            a[2] = m2[rr1 * 32 + ks * 8 + tig + 4];
            a[3] = m2[rr2 * 32 + ks * 8 + tig + 4];
            mma16816(c[0], a, Bl[ks][0]);
            mma16816(c[1], a, Bl[ks][1]);
        }
#pragma unroll
        for (int ks = 0; ks < 4; ++ks) {
            uint32_t a[4];
            a[0] = r2[rr1 * 32 + ks * 8 + tig];
            a[1] = r2[rr2 * 32 + ks * 8 + tig];
            a[2] = r2[rr1 * 32 + ks * 8 + tig + 4];
            a[3] = r2[rr2 * 32 + ks * 8 + tig + 4];
            mma16816(c[0], a, Br[ks][0]);
            mma16816(c[1], a, Br[ks][1]);
        }
#pragma unroll
        for (int nst = 0; nst < 2; ++nst) {
            int col = nbase + nst * 8 + 2 * tig;
            float o0 = fmaxf(c[nst][0], 0.0f), o1 = fmaxf(c[nst][1], 0.0f);
            float p0 = fmaxf(c[nst][2], 0.0f), p1 = fmaxf(c[nst][3], 0.0f);
            if (row1 < n)
                ((__half2*)out16)[row1 * 32 + (col >> 1)] = __floats2half2_rn(o0, o1);
            if (row2 < n)
                ((__half2*)out16)[row2 * 32 + (col >> 1)] = __floats2half2_rn(p0, p1);
        }
    }
}

// ---------------- gather v3: LDG.128, 4 edges per warp-pass -------------------
// lane layout: g = lane>>3 picks edge j*4+g, s = lane&7 loads row bytes
// [16s,16s+16) as uint4. 8 fp32 accumulators per lane; fold groups by shfl.
template <bool USE_W>
__global__ void __launch_bounds__(256)
gather_kernel(const __half* __restrict__ hin16,
              __half* __restrict__ mv16, int n) {
    __shared__ int2 sedge[8][32];
    int warp = threadIdx.x >> 5;
    int lane = threadIdx.x & 31;
    int g    = lane >> 3;
    int s    = lane & 7;
    int node = blockIdx.x * 8 + warp;
    if (node >= n) return;

    const uint4* h4 = (const uint4*)hin16;   // 8 uint4 per 64-col row
    int start = g_rowstart[node];
    int end   = g_rowstart[node + 1];

    float acc[8];
#pragma unroll
    for (int k = 0; k < 8; ++k) acc[k] = 0.0f;

    for (int i0 = start; i0 < end; i0 += 32) {
        int mm = min(32, end - i0);
        int2 eg = make_int2(0, 0);
        if (lane < mm) eg = g_edge[i0 + lane];
        sedge[warp][lane] = eg;
        __syncwarp();

        int2  e[8];
        uint4 v[8];
#pragma unroll
        for (int j = 0; j < 8; ++j) e[j] = sedge[warp][j * 4 + g];
#pragma unroll
        for (int j = 0; j < 8; ++j) v[j] = h4[(size_t)e[j].x * 8 + s];
#pragma unroll
        for (int j = 0; j < 8; ++j) {
            float w = (j * 4 + g < mm)
                        ? (USE_W ? __int_as_float(e[j].y) : 1.0f) : 0.0f;
            float2 f0 = __half22float2(*reinterpret_cast<__half2*>(&v[j].x));
            float2 f1 = __half22float2(*reinterpret_cast<__half2*>(&v[j].y));
            float2 f2 = __half22float2(*reinterpret_cast<__half2*>(&v[j].z));
            float2 f3 = __half22float2(*reinterpret_cast<__half2*>(&v[j].w));
            acc[0] = fmaf(w, f0.x, acc[0]); acc[1] = fmaf(w, f0.y, acc[1]);
            acc[2] = fmaf(w, f1.x, acc[2]); acc[3] = fmaf(w, f1.y, acc[3]);
            acc[4] = fmaf(w, f2.x, acc[4]); acc[5] = fmaf(w, f2.y, acc[5]);
            acc[6] = fmaf(w, f3.x, acc[6]); acc[7] = fmaf(w, f3.y, acc[7]);
        }
        __syncwarp();
    }

    // fold the 4 edge-groups (lanes with equal s)
#pragma unroll
    for (int k = 0; k < 8; ++k) {
        acc[k] += __shfl_xor_sync(~0u, acc[k], 8);
        acc[k] += __shfl_xor_sync(~0u, acc[k], 16);
    }
    float invd = 1.0f / fmaxf((float)(end - start), 1.0f);
    if (lane < 8) {
        uint4 o;
        o.x = f2h2(acc[0] * invd, acc[1] * invd);
        o.y = f2h2(acc[2] * invd, acc[3] * invd);
        o.z = f2h2(acc[4] * invd, acc[5] * invd);
        o.w = f2h2(acc[6] * invd, acc[7] * invd);
        ((uint4*)mv16)[(size_t)node * 8 + lane] = o;
    }
}

// ---------------- tensor transform (R8-proven, 128 thr) -----------------------
template <bool RELU, bool NORM, bool W16, bool WF32>
__global__ void __launch_bounds__(128)
transform_kernel(const __half* __restrict__ mv16,
                 const __half* __restrict__ root16,
                 const float* __restrict__ Wl,
                 const float* __restrict__ bl,
                 const float* __restrict__ Wr,
                 float* __restrict__ outf, int ostride, int ocols,
                 __half* __restrict__ out16, int n) {
    __shared__ __align__(16) float ssq[16][4];
    int warp = threadIdx.x >> 5;
    int lane = threadIdx.x & 31;
    int g    = lane >> 2;
    int tig  = lane & 3;
    int nbase = warp * 16;

    uint32_t Bl[4][2][2], Br[4][2][2];
#pragma unroll
    for (int ks = 0; ks < 4; ++ks)
#pragma unroll
        for (int nst = 0; nst < 2; ++nst) {
            int ncol = nbase + nst * 8 + g;
#pragma unroll
            for (int rr = 0; rr < 2; ++rr) {
                int k = ks * 16 + 2 * tig + rr * 8;
                Bl[ks][nst][rr] = f2h2(Wl[k * HD + ncol], Wl[(k + 1) * HD + ncol]);
                Br[ks][nst][rr] = f2h2(Wr[k * HD + ncol], Wr[(k + 1) * HD + ncol]);
            }
        }
    float bb[2][2];
#pragma unroll
    for (int nst = 0; nst < 2; ++nst) {
        bb[nst][0] = bl[nbase + nst * 8 + 2 * tig];
        bb[nst][1] = bl[nbase + nst * 8 + 2 * tig + 1];
    }

    const uint32_t* m2 = (const uint32_t*)mv16;
    const uint32_t* r2 = (const uint32_t*)root16;
    int ntiles = (n + 15) >> 4;

    for (int tile = blockIdx.x; tile < ntiles; tile += gridDim.x) {
        int row1 = tile * 16 + g;
        int row2 = row1 + 8;
        int rr1 = min(row1, n - 1);
        int rr2 = min(row2, n - 1);

        float c[2][4];
#pragma unroll
        for (int nst = 0; nst < 2; ++nst) {
            c[nst][0] = bb[nst][0]; c[nst][1] = bb[nst][1];
            c[nst][2] = bb[nst][0]; c[nst][3] = bb[nst][1];
        }
#pragma unroll
        for (int ks = 0; ks < 4; ++ks) {
            uint32_t a[4];
            a[0] = m2[rr1 * 32 + ks * 8 + tig];
            a[1] = m2[rr2 * 32 + ks * 8 + tig];
            a[2] = m2[rr1 * 32 + ks * 8 + tig + 4];
            a[3] = m2[rr2 * 32 + ks * 8 + tig + 4];
            mma16816(c[0], a, Bl[ks][0]);
            mma16816(c[1], a, Bl[ks][1]);
        }
#pragma unroll
        for (int ks = 0; ks < 4; ++ks) {
            uint32_t a[4];
            a[0] = r2[rr1 * 32 + ks * 8 + tig];
            a[1] = r2[rr2 * 32 + ks * 8 + tig];
            a[2] = r2[rr1 * 32 + ks * 8 + tig + 4];
            a[3] = r2[rr2 * 32 + ks * 8 + tig + 4];
            mma16816(c[0], a, Br[ks][0]);
            mma16816(c[1], a, Br[ks][1]);
        }

        float inv1 = 1.0f, inv2 = 1.0f;
        if (NORM) {
            float s1 = c[0][0] * c[0][0] + c[0][1] * c[0][1]
                     + c[1][0] * c[1][0] + c[1][1] * c[1][1];
            float s2 = c[0][2] * c[0][2] + c[0][3] * c[0][3]
                     + c[1][2] * c[1][2] + c[1][3] * c[1][3];
            s1 += __shfl_xor_sync(~0u, s1, 1); s1 += __shfl_xor_sync(~0u, s1, 2);
            s2 += __shfl_xor_sync(~0u, s2, 1); s2 += __shfl_xor_sync(~0u, s2, 2);
            if (tig == 0) { ssq[g][warp] = s1; ssq[g + 8][warp] = s2; }
            __syncthreads();
            float4 q1 = *(const float4*)ssq[g];
            float4 q2 = *(const float4*)ssq[g + 8];
            inv1 = 1.0f / fmaxf(sqrtf(q1.x + q1.y + q1.z + q1.w), 1e-12f);
            inv2 = 1.0f / fmaxf(sqrtf(q2.x + q2.y + q2.z + q2.w), 1e-12f);
            __syncthreads();
        }

#pragma unroll
        for (int nst = 0; nst < 2; ++nst) {
            int col = nbase + nst * 8 + 2 * tig;
            float o0 = c[nst][0] * inv1, o1 = c[nst][1] * inv1;
            float p0 = c[nst][2] * inv2, p1 = c[nst][3] * inv2;
            if (RELU) {
                o0 = fmaxf(o0, 0.0f); o1 = fmaxf(o1, 0.0f);
                p0 = fmaxf(p0, 0.0f); p1 = fmaxf(p1, 0.0f);
            }
            if (W16) {
                if (row1 < n)
                    ((__half2*)out16)[row1 * 32 + (col >> 1)] = __floats2half2_rn(o0, o1);
                if (row2 < n)
                    ((__half2*)out16)[row2 * 32 + (col >> 1)] = __floats2half2_rn(p0, p1);
            }
            if (WF32) {
                if (row1 < n && col < ocols) {
                    outf[(size_t)row1 * ostride + col] = o0;
                    if (col + 1 < ocols) outf[(size_t)row1 * ostride + col + 1] = o1;
                }
                if (row2 < n && col < ocols) {
                    outf[(size_t)row2 * ostride + col] = p0;
                    if (col + 1 < ocols) outf[(size_t)row2 * ostride + col + 1] = p1;
                }
            }
        }
    }
}

// ---------------- launch ---------------------------------------------------------
extern "C" void kernel_launch(void* const* d_in, const int* in_sizes, int n_in,
                              void* d_out, int out_size) {
    const float* x    = (const float*)d_in[0];
    const int*   ei   = (const int*)d_in[1];     // int32 [2, E]
    const float* ew   = (const float*)d_in[2];
    const float* embW = (const float*)d_in[3];
    const float* embB = (const float*)d_in[4];
    const float* Wl1 = (const float*)d_in[5];
    const float* bl1 = (const float*)d_in[6];
    const float* Wr1 = (const float*)d_in[7];
    const float* Wl2 = (const float*)d_in[8];
    const float* bl2 = (const float*)d_in[9];
    const float* Wr2 = (const float*)d_in[10];
    const float* Wl3 = (const float*)d_in[11];
    const float* bl3 = (const float*)d_in[12];
    const float* Wr3 = (const float*)d_in[13];
    const float* Wl4 = (const float*)d_in[14];
    const float* bl4 = (const float*)d_in[15];
    const float* Wr4 = (const float*)d_in[16];

    int n = in_sizes[0] / FIN;
    int e = in_sizes[2];

    __half *hA16, *hB16, *mv16;
    float *Wemb, *W4, *b4; int* cnt;
    cudaGetSymbolAddress((void**)&hA16, g_hA16);
    cudaGetSymbolAddress((void**)&hB16, g_hB16);
    cudaGetSymbolAddress((void**)&mv16, g_mv16);
    cudaGetSymbolAddress((void**)&Wemb, g_Wemb);
    cudaGetSymbolAddress((void**)&W4,   g_W4);
    cudaGetSymbolAddress((void**)&b4,   g_b4);
    cudaGetSymbolAddress((void**)&cnt,  g_cnt);

    cudaMemsetAsync(cnt, 0, (size_t)n * sizeof(int));

    // K1: convert | pad | hist
    int CB = (n * HD / 4 + 255) / 256;
    int HB = (e / 4 + 255) / 256;
    prep_kernel<<<CB + 32 + HB, 256>>>(x, embW, Wl4, bl4, Wr4, ei, n, e, CB);

    int nb = (n + 1023) / 1024;
    block_sum_kernel<<<nb, 256>>>(n);
    scan_bsum_kernel<<<1, 128>>>(nb, n);
    write_rowstart_kernel<<<nb, 256>>>(n);

    // K2: embed transform | fill
    const int TB = 1036;
    int FB = (e / 4 + 255) / 256;
    embed_fill_kernel<<<TB + FB, 256>>>(ei, ew, Wemb, embB, Wemb + HD * HD,
                                        hA16, n, e, TB);

    const int TG = 1480;
    int ggrid = (n + 7) / 8;
    gather_kernel<true><<<ggrid, 256>>>(hA16, mv16, n);
    transform_kernel<true, true, true, false><<<TG, 128>>>(
        mv16, hA16, Wl1, bl1, Wr1, nullptr, 0, 0, hB16, n);
    gather_kernel<true><<<ggrid, 256>>>(hB16, mv16, n);
    transform_kernel<true, true, true, false><<<TG, 128>>>(
        mv16, hB16, Wl2, bl2, Wr2, nullptr, 0, 0, hA16, n);
    gather_kernel<true><<<ggrid, 256>>>(hA16, mv16, n);
    transform_kernel<true, true, true, false><<<TG, 128>>>(
        mv16, hA16, Wl3, bl3, Wr3, nullptr, 0, 0, hB16, n);
    gather_kernel<false><<<ggrid, 256>>>(hB16, mv16, n);
    transform_kernel<false, true, false, true><<<TG, 128>>>(
        mv16, hB16, W4, b4, W4 + HD * HD, (float*)d_out, 18, 18, nullptr, n);
}

// round 13
// speedup vs baseline: 1.0271x; 1.0097x over previous
#include <cuda_runtime.h>
#include <cuda_fp16.h>
#include <cstdint>

#define FIN 100
#define HD  64
#define NMAX 100000
#define EMAX 3200000
#define NBMAX 128

// ---------------- scratch (device globals) -----------------------------------
__device__ __half g_hA16[NMAX * HD];
__device__ __half g_hB16[NMAX * HD];
__device__ __half g_mv16[NMAX * HD];
__device__ __half g_xlo16[NMAX * HD];
__device__ __half g_xhi16[NMAX * HD];
__device__ float  g_Wemb[2 * HD * HD];
__device__ float  g_W4[2 * HD * HD];
__device__ float  g_b4[HD];
__device__ int    g_cnt[NMAX];
__device__ int    g_rowstart[NMAX + 1];
__device__ int    g_cursor[NMAX];
__device__ int    g_scanpub[NBMAX];      // per-chunk sums, -1 = not ready
__device__ int2   g_edge[EMAX];

// ---------------- helpers ------------------------------------------------------
__device__ __forceinline__ uint32_t f2h2(float lo, float hi) {
    __half2 h = __floats2half2_rn(lo, hi);
    return *reinterpret_cast<uint32_t*>(&h);
}

__device__ __forceinline__ void mma16816(float c[4], const uint32_t a[4],
                                         const uint32_t b[2]) {
    asm volatile(
        "mma.sync.aligned.m16n8k16.row.col.f32.f16.f16.f32 "
        "{%0,%1,%2,%3}, {%4,%5,%6,%7}, {%8,%9}, {%0,%1,%2,%3};\n"
        : "+f"(c[0]), "+f"(c[1]), "+f"(c[2]), "+f"(c[3])
        : "r"(a[0]), "r"(a[1]), "r"(a[2]), "r"(a[3]), "r"(b[0]), "r"(b[1]));
}

// ---------------- K1: convert_x | pad | hist (block-range roles) ---------------
__global__ void prep_kernel(const float* __restrict__ x,
                            const float* __restrict__ embW,
                            const float* __restrict__ Wl4,
                            const float* __restrict__ bl4,
                            const float* __restrict__ Wr4,
                            const int* __restrict__ ei,
                            int n, int e, int CB) {
    int bid = blockIdx.x;
    if (bid < CB) {
        int base = (bid * 256 + threadIdx.x) * 4;
        if (base >= n * HD) return;
        int node = base >> 6;
        int c    = base & 63;
        const float* xr = x + (size_t)node * FIN;
        float4 lo = *(const float4*)(xr + c);
        uint2 lo2 = make_uint2(f2h2(lo.x, lo.y), f2h2(lo.z, lo.w));
        *(uint2*)(g_xlo16 + base) = lo2;
        float4 hi = make_float4(0.f, 0.f, 0.f, 0.f);
        if (c < FIN - HD) hi = *(const float4*)(xr + HD + c);
        uint2 hi2 = make_uint2(f2h2(hi.x, hi.y), f2h2(hi.z, hi.w));
        *(uint2*)(g_xhi16 + base) = hi2;
    } else if (bid < CB + 32) {
        int tid = (bid - CB) * 256 + threadIdx.x;
        if (tid < NBMAX) g_scanpub[tid] = -1;    // reset scan publish slots
        if (tid < 2 * HD * HD) {
            int k = tid >> 6, c = tid & 63;
            g_Wemb[tid] = (k < FIN) ? embW[k * HD + c] : 0.0f;
        }
        if (tid < HD * HD) {
            int k = tid >> 6, c = tid & 63;
            g_W4[tid]           = (c < 18) ? Wl4[k * 18 + c] : 0.0f;
            g_W4[HD * HD + tid] = (c < 18) ? Wr4[k * 18 + c] : 0.0f;
        }
        if (tid < HD) g_b4[tid] = (tid < 18) ? bl4[tid] : 0.0f;
    } else {
        int base = ((bid - CB - 32) * 256 + threadIdx.x) * 4;
#pragma unroll
        for (int j = 0; j < 4; ++j) {
            int i = base + j;
            if (i < e) {
                int dst = ei[e + i];
                dst = min(max(dst, 0), n - 1);
                atomicAdd(&g_cnt[dst], 1);
            }
        }
    }
}

// ---------------- fused single-kernel scan --------------------------------------
// grid = nb (<=128, all co-resident), 256 thr. Each block: local scan of its
// 1024-chunk, publish chunk sum, spin-wait on predecessors (1 thread per
// predecessor slot), block-reduce offsets, write rowstart + cursor.
__global__ void scan_fused_kernel(int n, int nb) {
    __shared__ int sw[8];
    __shared__ int sred[8];
    __shared__ int soff;
    int b    = blockIdx.x;
    int tid  = threadIdx.x;
    int lane = tid & 31;
    int warp = tid >> 5;
    int i0 = b * 1024 + tid * 4;
    int c[4];
    int ts = 0;
#pragma unroll
    for (int j = 0; j < 4; ++j) {
        int i = i0 + j;
        c[j] = (i < n) ? g_cnt[i] : 0;
        ts += c[j];
    }
    // block scan of per-thread sums
    int x = ts;
#pragma unroll
    for (int o = 1; o < 32; o <<= 1) {
        int y = __shfl_up_sync(~0u, x, o);
        if (lane >= o) x += y;
    }
    if (lane == 31) sw[warp] = x;
    __syncthreads();
    if (tid < 8) {
        int y = sw[tid];
#pragma unroll
        for (int o = 1; o < 8; o <<= 1) {
            int z = __shfl_up_sync(0xFF, y, o);
            if (tid >= o) y += z;
        }
        sw[tid] = y;
    }
    __syncthreads();
    int total = sw[7];
    // publish this chunk's sum
    if (tid == 0) atomicExch(&g_scanpub[b], total);
    // wait for predecessors (distinct slot per thread) and sum them
    int pv = 0;
    if (tid < b) {
        int v;
        do { v = atomicAdd(&g_scanpub[tid], 0); } while (v < 0);
        pv = v;
    }
#pragma unroll
    for (int o = 16; o; o >>= 1) pv += __shfl_xor_sync(~0u, pv, o);
    if (lane == 0) sred[warp] = pv;
    __syncthreads();
    if (tid == 0) {
        int t = 0;
#pragma unroll
        for (int w = 0; w < 8; ++w) t += sred[w];
        soff = t;
    }
    __syncthreads();
    int offset = soff;
    int run = offset + (x - ts) + (warp > 0 ? sw[warp - 1] : 0);
#pragma unroll
    for (int j = 0; j < 4; ++j) {
        int i = i0 + j;
        if (i < n) {
            g_rowstart[i] = run;
            g_cursor[i]   = run;
        }
        run += c[j];
    }
    if (b == nb - 1 && tid == 0) g_rowstart[n] = offset + total;
}

// ---------------- K2: embed transform | fill (block-range roles) ---------------
__global__ void __launch_bounds__(256)
embed_fill_kernel(const int* __restrict__ ei, const float* __restrict__ w,
                  const float* __restrict__ Wl, const float* __restrict__ bl,
                  const float* __restrict__ Wr,
                  __half* __restrict__ out16, int n, int e, int TB) {
    int bid = blockIdx.x;
    if (bid >= TB) {   // ---- fill role ----
        int base = ((bid - TB) * 256 + threadIdx.x) * 4;
#pragma unroll
        for (int j = 0; j < 4; ++j) {
            int i = base + j;
            if (i < e) {
                int dst = ei[e + i];
                int src = ei[i];
                dst = min(max(dst, 0), n - 1);
                src = min(max(src, 0), n - 1);
                int pos = atomicAdd(&g_cursor[dst], 1);
                pos = min(max(pos, 0), EMAX - 1);
                g_edge[pos] = make_int2(src, __float_as_int(w[i]));
            }
        }
        return;
    }
    // ---- embed transform role ----
    int warp  = threadIdx.x >> 5;
    int lane  = threadIdx.x & 31;
    int g     = lane >> 2;
    int tig   = lane & 3;
    int sub   = warp & 3;
    int grp   = warp >> 2;
    int nbase = sub * 16;

    uint32_t Bl[4][2][2], Br[4][2][2];
#pragma unroll
    for (int ks = 0; ks < 4; ++ks)
#pragma unroll
        for (int nst = 0; nst < 2; ++nst) {
            int ncol = nbase + nst * 8 + g;
#pragma unroll
            for (int rr = 0; rr < 2; ++rr) {
                int k = ks * 16 + 2 * tig + rr * 8;
                Bl[ks][nst][rr] = f2h2(Wl[k * HD + ncol], Wl[(k + 1) * HD + ncol]);
                Br[ks][nst][rr] = f2h2(Wr[k * HD + ncol], Wr[(k + 1) * HD + ncol]);
            }
        }
    float bb[2][2];
#pragma unroll
    for (int nst = 0; nst < 2; ++nst) {
        bb[nst][0] = bl[nbase + nst * 8 + 2 * tig];
        bb[nst][1] = bl[nbase + nst * 8 + 2 * tig + 1];
    }

    const uint32_t* m2 = (const uint32_t*)g_xlo16;
    const uint32_t* r2 = (const uint32_t*)g_xhi16;
    int ntiles = (n + 15) >> 4;
    int npairs = (ntiles + 1) >> 1;

    for (int pr = bid; pr < npairs; pr += TB) {
        int tile = pr * 2 + grp;
        if (tile >= ntiles) continue;
        int row1 = tile * 16 + g;
        int row2 = row1 + 8;
        int rr1 = min(row1, n - 1);
        int rr2 = min(row2, n - 1);

        float c[2][4];
#pragma unroll
        for (int nst = 0; nst < 2; ++nst) {
            c[nst][0] = bb[nst][0]; c[nst][1] = bb[nst][1];
            c[nst][2] = bb[nst][0]; c[nst][3] = bb[nst][1];
        }
#pragma unroll
        for (int ks = 0; ks < 4; ++ks) {
            uint32_t a[4];
            a[0] = m2[rr1 * 32 + ks * 8 + tig];
            a[1] = m2[rr2 * 32 + ks * 8 + tig];
            a[2] = m2[rr1 * 32 + ks * 8 + tig + 4];
            a[3] = m2[rr2 * 32 + ks * 8 + tig + 4];
            mma16816(c[0], a, Bl[ks][0]);
            mma16816(c[1], a, Bl[ks][1]);
        }
#pragma unroll
        for (int ks = 0; ks < 4; ++ks) {
            uint32_t a[4];
            a[0] = r2[rr1 * 32 + ks * 8 + tig];
            a[1] = r2[rr2 * 32 + ks * 8 + tig];
            a[2] = r2[rr1 * 32 + ks * 8 + tig + 4];
            a[3] = r2[rr2 * 32 + ks * 8 + tig + 4];
            mma16816(c[0], a, Br[ks][0]);
            mma16816(c[1], a, Br[ks][1]);
        }
#pragma unroll
        for (int nst = 0; nst < 2; ++nst) {
            int col = nbase + nst * 8 + 2 * tig;
            float o0 = fmaxf(c[nst][0], 0.0f), o1 = fmaxf(c[nst][1], 0.0f);
            float p0 = fmaxf(c[nst][2], 0.0f), p1 = fmaxf(c[nst][3], 0.0f);
            if (row1 < n)
                ((__half2*)out16)[row1 * 32 + (col >> 1)] = __floats2half2_rn(o0, o1);
            if (row2 < n)
                ((__half2*)out16)[row2 * 32 + (col >> 1)] = __floats2half2_rn(p0, p1);
        }
    }
}

// ---------------- gather v4: LDG.128, unroll 2x4 (lower regs, 5 blocks/SM) ----
// lane layout: g = lane>>3 picks edge group, s = lane&7 loads row bytes
// [16s,16s+16) as uint4. Per-lane accumulation order identical to v3.
template <bool USE_W>
__global__ void __launch_bounds__(256)
gather_kernel(const __half* __restrict__ hin16,
              __half* __restrict__ mv16, int n) {
    __shared__ int2 sedge[8][32];
    int warp = threadIdx.x >> 5;
    int lane = threadIdx.x & 31;
    int g    = lane >> 3;
    int s    = lane & 7;
    int node = blockIdx.x * 8 + warp;
    if (node >= n) return;

    const uint4* h4 = (const uint4*)hin16;   // 8 uint4 per 64-col row
    int start = g_rowstart[node];
    int end   = g_rowstart[node + 1];

    float acc[8];
#pragma unroll
    for (int k = 0; k < 8; ++k) acc[k] = 0.0f;

    for (int i0 = start; i0 < end; i0 += 32) {
        int mm = min(32, end - i0);
        int2 eg = make_int2(0, 0);
        if (lane < mm) eg = g_edge[i0 + lane];
        sedge[warp][lane] = eg;
        __syncwarp();

#pragma unroll
        for (int half = 0; half < 2; ++half) {
            int2  e[4];
            uint4 v[4];
#pragma unroll
            for (int j = 0; j < 4; ++j) e[j] = sedge[warp][(half * 4 + j) * 4 + g];
#pragma unroll
            for (int j = 0; j < 4; ++j) v[j] = h4[(size_t)e[j].x * 8 + s];
#pragma unroll
            for (int j = 0; j < 4; ++j) {
                float w = ((half * 4 + j) * 4 + g < mm)
                            ? (USE_W ? __int_as_float(e[j].y) : 1.0f) : 0.0f;
                float2 f0 = __half22float2(*reinterpret_cast<__half2*>(&v[j].x));
                float2 f1 = __half22float2(*reinterpret_cast<__half2*>(&v[j].y));
                float2 f2 = __half22float2(*reinterpret_cast<__half2*>(&v[j].z));
                float2 f3 = __half22float2(*reinterpret_cast<__half2*>(&v[j].w));
                acc[0] = fmaf(w, f0.x, acc[0]); acc[1] = fmaf(w, f0.y, acc[1]);
                acc[2] = fmaf(w, f1.x, acc[2]); acc[3] = fmaf(w, f1.y, acc[3]);
                acc[4] = fmaf(w, f2.x, acc[4]); acc[5] = fmaf(w, f2.y, acc[5]);
                acc[6] = fmaf(w, f3.x, acc[6]); acc[7] = fmaf(w, f3.y, acc[7]);
            }
        }
        __syncwarp();
    }

    // fold the 4 edge-groups (lanes with equal s)
#pragma unroll
    for (int k = 0; k < 8; ++k) {
        acc[k] += __shfl_xor_sync(~0u, acc[k], 8);
        acc[k] += __shfl_xor_sync(~0u, acc[k], 16);
    }
    float invd = 1.0f / fmaxf((float)(end - start), 1.0f);
    if (lane < 8) {
        uint4 o;
        o.x = f2h2(acc[0] * invd, acc[1] * invd);
        o.y = f2h2(acc[2] * invd, acc[3] * invd);
        o.z = f2h2(acc[4] * invd, acc[5] * invd);
        o.w = f2h2(acc[6] * invd, acc[7] * invd);
        ((uint4*)mv16)[(size_t)node * 8 + lane] = o;
    }
}

// ---------------- tensor transform (128 thr; ssq double-buffered) --------------
template <bool RELU, bool NORM, bool W16, bool WF32>
__global__ void __launch_bounds__(128)
transform_kernel(const __half* __restrict__ mv16,
                 const __half* __restrict__ root16,
                 const float* __restrict__ Wl,
                 const float* __restrict__ bl,
                 const float* __restrict__ Wr,
                 float* __restrict__ outf, int ostride, int ocols,
                 __half* __restrict__ out16, int n) {
    __shared__ __align__(16) float ssq[2][16][4];
    int warp = threadIdx.x >> 5;
    int lane = threadIdx.x & 31;
    int g    = lane >> 2;
    int tig  = lane & 3;
    int nbase = warp * 16;

    uint32_t Bl[4][2][2], Br[4][2][2];
#pragma unroll
    for (int ks = 0; ks < 4; ++ks)
#pragma unroll
        for (int nst = 0; nst < 2; ++nst) {
            int ncol = nbase + nst * 8 + g;
#pragma unroll
            for (int rr = 0; rr < 2; ++rr) {
                int k = ks * 16 + 2 * tig + rr * 8;
                Bl[ks][nst][rr] = f2h2(Wl[k * HD + ncol], Wl[(k + 1) * HD + ncol]);
                Br[ks][nst][rr] = f2h2(Wr[k * HD + ncol], Wr[(k + 1) * HD + ncol]);
            }
        }
    float bb[2][2];
#pragma unroll
    for (int nst = 0; nst < 2; ++nst) {
        bb[nst][0] = bl[nbase + nst * 8 + 2 * tig];
        bb[nst][1] = bl[nbase + nst * 8 + 2 * tig + 1];
    }

    const uint32_t* m2 = (const uint32_t*)mv16;
    const uint32_t* r2 = (const uint32_t*)root16;
    int ntiles = (n + 15) >> 4;
    int pb = 0;

    for (int tile = blockIdx.x; tile < ntiles; tile += gridDim.x) {
        int row1 = tile * 16 + g;
        int row2 = row1 + 8;
        int rr1 = min(row1, n - 1);
        int rr2 = min(row2, n - 1);

        float c[2][4];
#pragma unroll
        for (int nst = 0; nst < 2; ++nst) {
            c[nst][0] = bb[nst][0]; c[nst][1] = bb[nst][1];
            c[nst][2] = bb[nst][0]; c[nst][3] = bb[nst][1];
        }
#pragma unroll
        for (int ks = 0; ks < 4; ++ks) {
            uint32_t a[4];
            a[0] = m2[rr1 * 32 + ks * 8 + tig];
            a[1] = m2[rr2 * 32 + ks * 8 + tig];
            a[2] = m2[rr1 * 32 + ks * 8 + tig + 4];
            a[3] = m2[rr2 * 32 + ks * 8 + tig + 4];
            mma16816(c[0], a, Bl[ks][0]);
            mma16816(c[1], a, Bl[ks][1]);
        }
#pragma unroll
        for (int ks = 0; ks < 4; ++ks) {
            uint32_t a[4];
            a[0] = r2[rr1 * 32 + ks * 8 + tig];
            a[1] = r2[rr2 * 32 + ks * 8 + tig];
            a[2] = r2[rr1 * 32 + ks * 8 + tig + 4];
            a[3] = r2[rr2 * 32 + ks * 8 + tig + 4];
            mma16816(c[0], a, Br[ks][0]);
            mma16816(c[1], a, Br[ks][1]);
        }

        float inv1 = 1.0f, inv2 = 1.0f;
        if (NORM) {
            float s1 = c[0][0] * c[0][0] + c[0][1] * c[0][1]
                     + c[1][0] * c[1][0] + c[1][1] * c[1][1];
            float s2 = c[0][2] * c[0][2] + c[0][3] * c[0][3]
                     + c[1][2] * c[1][2] + c[1][3] * c[1][3];
            s1 += __shfl_xor_sync(~0u, s1, 1); s1 += __shfl_xor_sync(~0u, s1, 2);
            s2 += __shfl_xor_sync(~0u, s2, 1); s2 += __shfl_xor_sync(~0u, s2, 2);
            if (tig == 0) { ssq[pb][g][warp] = s1; ssq[pb][g + 8][warp] = s2; }
            __syncthreads();
            float4 q1 = *(const float4*)ssq[pb][g];
            float4 q2 = *(const float4*)ssq[pb][g + 8];
            inv1 = 1.0f / fmaxf(sqrtf(q1.x + q1.y + q1.z + q1.w), 1e-12f);
            inv2 = 1.0f / fmaxf(sqrtf(q2.x + q2.y + q2.z + q2.w), 1e-12f);
            pb ^= 1;   // double-buffer: no trailing barrier needed
        }

#pragma unroll
        for (int nst = 0; nst < 2; ++nst) {
            int col = nbase + nst * 8 + 2 * tig;
            float o0 = c[nst][0] * inv1, o1 = c[nst][1] * inv1;
            float p0 = c[nst][2] * inv2, p1 = c[nst][3] * inv2;
            if (RELU) {
                o0 = fmaxf(o0, 0.0f); o1 = fmaxf(o1, 0.0f);
                p0 = fmaxf(p0, 0.0f); p1 = fmaxf(p1, 0.0f);
            }
            if (W16) {
                if (row1 < n)
                    ((__half2*)out16)[row1 * 32 + (col >> 1)] = __floats2half2_rn(o0, o1);
                if (row2 < n)
                    ((__half2*)out16)[row2 * 32 + (col >> 1)] = __floats2half2_rn(p0, p1);
            }
            if (WF32) {
                if (row1 < n && col < ocols) {
                    outf[(size_t)row1 * ostride + col] = o0;
                    if (col + 1 < ocols) outf[(size_t)row1 * ostride + col + 1] = o1;
                }
                if (row2 < n && col < ocols) {
                    outf[(size_t)row2 * ostride + col] = p0;
                    if (col + 1 < ocols) outf[(size_t)row2 * ostride + col + 1] = p1;
                }
            }
        }
    }
}

// ---------------- launch ---------------------------------------------------------
extern "C" void kernel_launch(void* const* d_in, const int* in_sizes, int n_in,
                              void* d_out, int out_size) {
    const float* x    = (const float*)d_in[0];
    const int*   ei   = (const int*)d_in[1];     // int32 [2, E]
    const float* ew   = (const float*)d_in[2];
    const float* embW = (const float*)d_in[3];
    const float* embB = (const float*)d_in[4];
    const float* Wl1 = (const float*)d_in[5];
    const float* bl1 = (const float*)d_in[6];
    const float* Wr1 = (const float*)d_in[7];
    const float* Wl2 = (const float*)d_in[8];
    const float* bl2 = (const float*)d_in[9];
    const float* Wr2 = (const float*)d_in[10];
    const float* Wl3 = (const float*)d_in[11];
    const float* bl3 = (const float*)d_in[12];
    const float* Wr3 = (const float*)d_in[13];
    const float* Wl4 = (const float*)d_in[14];
    const float* bl4 = (const float*)d_in[15];
    const float* Wr4 = (const float*)d_in[16];

    int n = in_sizes[0] / FIN;
    int e = in_sizes[2];

    __half *hA16, *hB16, *mv16;
    float *Wemb, *W4, *b4; int* cnt;
    cudaGetSymbolAddress((void**)&hA16, g_hA16);
    cudaGetSymbolAddress((void**)&hB16, g_hB16);
    cudaGetSymbolAddress((void**)&mv16, g_mv16);
    cudaGetSymbolAddress((void**)&Wemb, g_Wemb);
    cudaGetSymbolAddress((void**)&W4,   g_W4);
    cudaGetSymbolAddress((void**)&b4,   g_b4);
    cudaGetSymbolAddress((void**)&cnt,  g_cnt);

    cudaMemsetAsync(cnt, 0, (size_t)n * sizeof(int));

    // K1: convert | pad(+scan-slot reset) | hist
    int CB = (n * HD / 4 + 255) / 256;
    int HB = (e / 4 + 255) / 256;
    prep_kernel<<<CB + 32 + HB, 256>>>(x, embW, Wl4, bl4, Wr4, ei, n, e, CB);

    // K2: fused scan (single kernel, co-resident blocks)
    int nb = (n + 1023) / 1024;
    scan_fused_kernel<<<nb, 256>>>(n, nb);

    // K3: embed transform | fill
    const int TB = 1036;
    int FB = (e / 4 + 255) / 256;
    embed_fill_kernel<<<TB + FB, 256>>>(ei, ew, Wemb, embB, Wemb + HD * HD,
                                        hA16, n, e, TB);

    const int TG = 1480;
    int ggrid = (n + 7) / 8;
    gather_kernel<true><<<ggrid, 256>>>(hA16, mv16, n);
    transform_kernel<true, true, true, false><<<TG, 128>>>(
        mv16, hA16, Wl1, bl1, Wr1, nullptr, 0, 0, hB16, n);
    gather_kernel<true><<<ggrid, 256>>>(hB16, mv16, n);
    transform_kernel<true, true, true, false><<<TG, 128>>>(
        mv16, hB16, Wl2, bl2, Wr2, nullptr, 0, 0, hA16, n);
    gather_kernel<true><<<ggrid, 256>>>(hA16, mv16, n);
    transform_kernel<true, true, true, false><<<TG, 128>>>(
        mv16, hA16, Wl3, bl3, Wr3, nullptr, 0, 0, hB16, n);
    gather_kernel<false><<<ggrid, 256>>>(hB16, mv16, n);
    transform_kernel<false, true, false, true><<<TG, 128>>>(
        mv16, hB16, W4, b4, W4 + HD * HD, (float*)d_out, 18, 18, nullptr, n);
}

// round 14
// speedup vs baseline: 1.0444x; 1.0169x over previous
#include <cuda_runtime.h>
#include <cuda_fp16.h>
#include <cstdint>

#define FIN 100
#define HD  64
#define NMAX 100000
#define EMAX 3200000
#define NBMAX 128

// ---------------- scratch (device globals) -----------------------------------
__device__ __half g_hA16[NMAX * HD];
__device__ __half g_hB16[NMAX * HD];
__device__ __half g_mv16[NMAX * HD];
__device__ __half g_xlo16[NMAX * HD];
__device__ __half g_xhi16[NMAX * HD];
__device__ float  g_Wemb[2 * HD * HD];
__device__ float  g_W4[2 * HD * HD];
__device__ float  g_b4[HD];
__device__ int    g_cnt[NMAX];
__device__ int    g_rowstart[NMAX + 1];
__device__ int    g_cursor[NMAX];
__device__ int    g_scanpub[NBMAX];      // per-chunk sums, -1 = not ready
__device__ int2   g_edge[EMAX];

// ---------------- helpers ------------------------------------------------------
__device__ __forceinline__ uint32_t f2h2(float lo, float hi) {
    __half2 h = __floats2half2_rn(lo, hi);
    return *reinterpret_cast<uint32_t*>(&h);
}

__device__ __forceinline__ void mma16816(float c[4], const uint32_t a[4],
                                         const uint32_t b[2]) {
    asm volatile(
        "mma.sync.aligned.m16n8k16.row.col.f32.f16.f16.f32 "
        "{%0,%1,%2,%3}, {%4,%5,%6,%7}, {%8,%9}, {%0,%1,%2,%3};\n"
        : "+f"(c[0]), "+f"(c[1]), "+f"(c[2]), "+f"(c[3])
        : "r"(a[0]), "r"(a[1]), "r"(a[2]), "r"(a[3]), "r"(b[0]), "r"(b[1]));
}

__device__ __forceinline__ unsigned long long pack2f(float lo, float hi) {
    unsigned long long r;
    asm("mov.b64 %0, {%1, %2};" : "=l"(r) : "f"(lo), "f"(hi));
    return r;
}
__device__ __forceinline__ unsigned long long pack2u(uint32_t lo, uint32_t hi) {
    unsigned long long r;
    asm("mov.b64 %0, {%1, %2};" : "=l"(r) : "r"(lo), "r"(hi));
    return r;
}
__device__ __forceinline__ void ffma2(unsigned long long& acc,
                                      unsigned long long a,
                                      unsigned long long b) {
    asm("fma.rn.f32x2 %0, %1, %2, %0;" : "+l"(acc) : "l"(a), "l"(b));
}
__device__ __forceinline__ void unpack2f(float& lo, float& hi,
                                         unsigned long long v) {
    asm("mov.b64 {%0, %1}, %2;" : "=f"(lo), "=f"(hi) : "l"(v));
}

// ---------------- K1: convert_x | pad | hist (block-range roles) ---------------
__global__ void prep_kernel(const float* __restrict__ x,
                            const float* __restrict__ embW,
                            const float* __restrict__ Wl4,
                            const float* __restrict__ bl4,
                            const float* __restrict__ Wr4,
                            const int* __restrict__ ei,
                            int n, int e, int CB) {
    int bid = blockIdx.x;
    if (bid < CB) {
        int base = (bid * 256 + threadIdx.x) * 4;
        if (base >= n * HD) return;
        int node = base >> 6;
        int c    = base & 63;
        const float* xr = x + (size_t)node * FIN;
        float4 lo = *(const float4*)(xr + c);
        uint2 lo2 = make_uint2(f2h2(lo.x, lo.y), f2h2(lo.z, lo.w));
        *(uint2*)(g_xlo16 + base) = lo2;
        float4 hi = make_float4(0.f, 0.f, 0.f, 0.f);
        if (c < FIN - HD) hi = *(const float4*)(xr + HD + c);
        uint2 hi2 = make_uint2(f2h2(hi.x, hi.y), f2h2(hi.z, hi.w));
        *(uint2*)(g_xhi16 + base) = hi2;
    } else if (bid < CB + 32) {
        int tid = (bid - CB) * 256 + threadIdx.x;
        if (tid < NBMAX) g_scanpub[tid] = -1;    // reset scan publish slots
        if (tid < 2 * HD * HD) {
            int k = tid >> 6, c = tid & 63;
            g_Wemb[tid] = (k < FIN) ? embW[k * HD + c] : 0.0f;
        }
        if (tid < HD * HD) {
            int k = tid >> 6, c = tid & 63;
            g_W4[tid]           = (c < 18) ? Wl4[k * 18 + c] : 0.0f;
            g_W4[HD * HD + tid] = (c < 18) ? Wr4[k * 18 + c] : 0.0f;
        }
        if (tid < HD) g_b4[tid] = (tid < 18) ? bl4[tid] : 0.0f;
    } else {
        int base = ((bid - CB - 32) * 256 + threadIdx.x) * 4;
#pragma unroll
        for (int j = 0; j < 4; ++j) {
            int i = base + j;
            if (i < e) {
                int dst = ei[e + i];
                dst = min(max(dst, 0), n - 1);
                atomicAdd(&g_cnt[dst], 1);
            }
        }
    }
}

// ---------------- fused single-kernel scan --------------------------------------
__global__ void scan_fused_kernel(int n, int nb) {
    __shared__ int sw[8];
    __shared__ int sred[8];
    __shared__ int soff;
    int b    = blockIdx.x;
    int tid  = threadIdx.x;
    int lane = tid & 31;
    int warp = tid >> 5;
    int i0 = b * 1024 + tid * 4;
    int c[4];
    int ts = 0;
#pragma unroll
    for (int j = 0; j < 4; ++j) {
        int i = i0 + j;
        c[j] = (i < n) ? g_cnt[i] : 0;
        ts += c[j];
    }
    int x = ts;
#pragma unroll
    for (int o = 1; o < 32; o <<= 1) {
        int y = __shfl_up_sync(~0u, x, o);
        if (lane >= o) x += y;
    }
    if (lane == 31) sw[warp] = x;
    __syncthreads();
    if (tid < 8) {
        int y = sw[tid];
#pragma unroll
        for (int o = 1; o < 8; o <<= 1) {
            int z = __shfl_up_sync(0xFF, y, o);
            if (tid >= o) y += z;
        }
        sw[tid] = y;
    }
    __syncthreads();
    int total = sw[7];
    if (tid == 0) atomicExch(&g_scanpub[b], total);
    int pv = 0;
    if (tid < b) {
        int v;
        do { v = atomicAdd(&g_scanpub[tid], 0); } while (v < 0);
        pv = v;
    }
#pragma unroll
    for (int o = 16; o; o >>= 1) pv += __shfl_xor_sync(~0u, pv, o);
    if (lane == 0) sred[warp] = pv;
    __syncthreads();
    if (tid == 0) {
        int t = 0;
#pragma unroll
        for (int w = 0; w < 8; ++w) t += sred[w];
        soff = t;
    }
    __syncthreads();
    int offset = soff;
    int run = offset + (x - ts) + (warp > 0 ? sw[warp - 1] : 0);
#pragma unroll
    for (int j = 0; j < 4; ++j) {
        int i = i0 + j;
        if (i < n) {
            g_rowstart[i] = run;
            g_cursor[i]   = run;
        }
        run += c[j];
    }
    if (b == nb - 1 && tid == 0) g_rowstart[n] = offset + total;
}

// ---------------- K2: embed transform | fill (block-range roles) ---------------
__global__ void __launch_bounds__(256)
embed_fill_kernel(const int* __restrict__ ei, const float* __restrict__ w,
                  const float* __restrict__ Wl, const float* __restrict__ bl,
                  const float* __restrict__ Wr,
                  __half* __restrict__ out16, int n, int e, int TB) {
    int bid = blockIdx.x;
    if (bid >= TB) {   // ---- fill role ----
        int base = ((bid - TB) * 256 + threadIdx.x) * 4;
#pragma unroll
        for (int j = 0; j < 4; ++j) {
            int i = base + j;
            if (i < e) {
                int dst = ei[e + i];
                int src = ei[i];
                dst = min(max(dst, 0), n - 1);
                src = min(max(src, 0), n - 1);
                int pos = atomicAdd(&g_cursor[dst], 1);
                pos = min(max(pos, 0), EMAX - 1);
                g_edge[pos] = make_int2(src, __float_as_int(w[i]));
            }
        }
        return;
    }
    // ---- embed transform role ----
    int warp  = threadIdx.x >> 5;
    int lane  = threadIdx.x & 31;
    int g     = lane >> 2;
    int tig   = lane & 3;
    int sub   = warp & 3;
    int grp   = warp >> 2;
    int nbase = sub * 16;

    uint32_t Bl[4][2][2], Br[4][2][2];
#pragma unroll
    for (int ks = 0; ks < 4; ++ks)
#pragma unroll
        for (int nst = 0; nst < 2; ++nst) {
            int ncol = nbase + nst * 8 + g;
#pragma unroll
            for (int rr = 0; rr < 2; ++rr) {
                int k = ks * 16 + 2 * tig + rr * 8;
                Bl[ks][nst][rr] = f2h2(Wl[k * HD + ncol], Wl[(k + 1) * HD + ncol]);
                Br[ks][nst][rr] = f2h2(Wr[k * HD + ncol], Wr[(k + 1) * HD + ncol]);
            }
        }
    float bb[2][2];
#pragma unroll
    for (int nst = 0; nst < 2; ++nst) {
        bb[nst][0] = bl[nbase + nst * 8 + 2 * tig];
        bb[nst][1] = bl[nbase + nst * 8 + 2 * tig + 1];
    }

    const uint32_t* m2 = (const uint32_t*)g_xlo16;
    const uint32_t* r2 = (const uint32_t*)g_xhi16;
    int ntiles = (n + 15) >> 4;
    int npairs = (ntiles + 1) >> 1;

    for (int pr = bid; pr < npairs; pr += TB) {
        int tile = pr * 2 + grp;
        if (tile >= ntiles) continue;
        int row1 = tile * 16 + g;
        int row2 = row1 + 8;
        int rr1 = min(row1, n - 1);
        int rr2 = min(row2, n - 1);

        float c[2][4];
#pragma unroll
        for (int nst = 0; nst < 2; ++nst) {
            c[nst][0] = bb[nst][0]; c[nst][1] = bb[nst][1];
            c[nst][2] = bb[nst][0]; c[nst][3] = bb[nst][1];
        }
#pragma unroll
        for (int ks = 0; ks < 4; ++ks) {
            uint32_t a[4];
            a[0] = m2[rr1 * 32 + ks * 8 + tig];
            a[1] = m2[rr2 * 32 + ks * 8 + tig];
            a[2] = m2[rr1 * 32 + ks * 8 + tig + 4];
            a[3] = m2[rr2 * 32 + ks * 8 + tig + 4];
            mma16816(c[0], a, Bl[ks][0]);
            mma16816(c[1], a, Bl[ks][1]);
        }
#pragma unroll
        for (int ks = 0; ks < 4; ++ks) {
            uint32_t a[4];
            a[0] = r2[rr1 * 32 + ks * 8 + tig];
            a[1] = r2[rr2 * 32 + ks * 8 + tig];
            a[2] = r2[rr1 * 32 + ks * 8 + tig + 4];
            a[3] = r2[rr2 * 32 + ks * 8 + tig + 4];
            mma16816(c[0], a, Br[ks][0]);
            mma16816(c[1], a, Br[ks][1]);
        }
#pragma unroll
        for (int nst = 0; nst < 2; ++nst) {
            int col = nbase + nst * 8 + 2 * tig;
            float o0 = fmaxf(c[nst][0], 0.0f), o1 = fmaxf(c[nst][1], 0.0f);
            float p0 = fmaxf(c[nst][2], 0.0f), p1 = fmaxf(c[nst][3], 0.0f);
            if (row1 < n)
                ((__half2*)out16)[row1 * 32 + (col >> 1)] = __floats2half2_rn(o0, o1);
            if (row2 < n)
                ((__half2*)out16)[row2 * 32 + (col >> 1)] = __floats2half2_rn(p0, p1);
        }
    }
}

// ---------------- gather v5: LDG.128 + staged weights + packed f32x2 FMA ------
// lane layout: g = lane>>3 picks edge group, s = lane&7 loads row bytes
// [16s,16s+16) as uint4. Weight bits staged in sedge (0.0 for padding, 1.0
// for unweighted layer) -> no per-edge predicate. fma.rn.f32x2 halves FMA
// issue count; numerics identical (2 IEEE FMAs per op, same order).
template <bool USE_W>
__global__ void __launch_bounds__(256)
gather_kernel(const __half* __restrict__ hin16,
              __half* __restrict__ mv16, int n) {
    __shared__ int2 sedge[8][32];
    int warp = threadIdx.x >> 5;
    int lane = threadIdx.x & 31;
    int g    = lane >> 3;
    int s    = lane & 7;
    int node = blockIdx.x * 8 + warp;
    if (node >= n) return;

    const uint4* h4 = (const uint4*)hin16;   // 8 uint4 per 64-col row
    int start = g_rowstart[node];
    int end   = g_rowstart[node + 1];

    unsigned long long acc64[4] = {0ull, 0ull, 0ull, 0ull};

    for (int i0 = start; i0 < end; i0 += 32) {
        int mm = min(32, end - i0);
        int2 eg = make_int2(0, 0);           // w = 0.0f for padding slots
        if (lane < mm) {
            eg = g_edge[i0 + lane];
            if (!USE_W) eg.y = 0x3f800000;   // w = 1.0f for valid slots
        }
        sedge[warp][lane] = eg;
        __syncwarp();

#pragma unroll
        for (int half = 0; half < 2; ++half) {
            int2  e[4];
            uint4 v[4];
#pragma unroll
            for (int j = 0; j < 4; ++j) e[j] = sedge[warp][(half * 4 + j) * 4 + g];
#pragma unroll
            for (int j = 0; j < 4; ++j) v[j] = h4[(size_t)e[j].x * 8 + s];
#pragma unroll
            for (int j = 0; j < 4; ++j) {
                unsigned long long ww = pack2u((uint32_t)e[j].y, (uint32_t)e[j].y);
                float2 f0 = __half22float2(*reinterpret_cast<__half2*>(&v[j].x));
                float2 f1 = __half22float2(*reinterpret_cast<__half2*>(&v[j].y));
                float2 f2 = __half22float2(*reinterpret_cast<__half2*>(&v[j].z));
                float2 f3 = __half22float2(*reinterpret_cast<__half2*>(&v[j].w));
                ffma2(acc64[0], pack2f(f0.x, f0.y), ww);
                ffma2(acc64[1], pack2f(f1.x, f1.y), ww);
                ffma2(acc64[2], pack2f(f2.x, f2.y), ww);
                ffma2(acc64[3], pack2f(f3.x, f3.y), ww);
            }
        }
        __syncwarp();
    }

    float acc[8];
#pragma unroll
    for (int k = 0; k < 4; ++k) unpack2f(acc[2 * k], acc[2 * k + 1], acc64[k]);

    // fold the 4 edge-groups (lanes with equal s)
#pragma unroll
    for (int k = 0; k < 8; ++k) {
        acc[k] += __shfl_xor_sync(~0u, acc[k], 8);
        acc[k] += __shfl_xor_sync(~0u, acc[k], 16);
    }
    float invd = 1.0f / fmaxf((float)(end - start), 1.0f);
    if (lane < 8) {
        uint4 o;
        o.x = f2h2(acc[0] * invd, acc[1] * invd);
        o.y = f2h2(acc[2] * invd, acc[3] * invd);
        o.z = f2h2(acc[4] * invd, acc[5] * invd);
        o.w = f2h2(acc[6] * invd, acc[7] * invd);
        ((uint4*)mv16)[(size_t)node * 8 + lane] = o;
    }
}

// ---------------- tensor transform (128 thr; ssq double-buffered) --------------
template <bool RELU, bool NORM, bool W16, bool WF32>
__global__ void __launch_bounds__(128)
transform_kernel(const __half* __restrict__ mv16,
                 const __half* __restrict__ root16,
                 const float* __restrict__ Wl,
                 const float* __restrict__ bl,
                 const float* __restrict__ Wr,
                 float* __restrict__ outf, int ostride, int ocols,
                 __half* __restrict__ out16, int n) {
    __shared__ __align__(16) float ssq[2][16][4];
    int warp = threadIdx.x >> 5;
    int lane = threadIdx.x & 31;
    int g    = lane >> 2;
    int tig  = lane & 3;
    int nbase = warp * 16;

    uint32_t Bl[4][2][2], Br[4][2][2];
#pragma unroll
    for (int ks = 0; ks < 4; ++ks)
#pragma unroll
        for (int nst = 0; nst < 2; ++nst) {
            int ncol = nbase + nst * 8 + g;
#pragma unroll
            for (int rr = 0; rr < 2; ++rr) {
                int k = ks * 16 + 2 * tig + rr * 8;
                Bl[ks][nst][rr] = f2h2(Wl[k * HD + ncol], Wl[(k + 1) * HD + ncol]);
                Br[ks][nst][rr] = f2h2(Wr[k * HD + ncol], Wr[(k + 1) * HD + ncol]);
            }
        }
    float bb[2][2];
#pragma unroll
    for (int nst = 0; nst < 2; ++nst) {
        bb[nst][0] = bl[nbase + nst * 8 + 2 * tig];
        bb[nst][1] = bl[nbase + nst * 8 + 2 * tig + 1];
    }

    const uint32_t* m2 = (const uint32_t*)mv16;
    const uint32_t* r2 = (const uint32_t*)root16;
    int ntiles = (n + 15) >> 4;
    int pb = 0;

    for (int tile = blockIdx.x; tile < ntiles; tile += gridDim.x) {
        int row1 = tile * 16 + g;
        int row2 = row1 + 8;
        int rr1 = min(row1, n - 1);
        int rr2 = min(row2, n - 1);

        float c[2][4];
#pragma unroll
        for (int nst = 0; nst < 2; ++nst) {
            c[nst][0] = bb[nst][0]; c[nst][1] = bb[nst][1];
            c[nst][2] = bb[nst][0]; c[nst][3] = bb[nst][1];
        }
#pragma unroll
        for (int ks = 0; ks < 4; ++ks) {
            uint32_t a[4];
            a[0] = m2[rr1 * 32 + ks * 8 + tig];
            a[1] = m2[rr2 * 32 + ks * 8 + tig];
            a[2] = m2[rr1 * 32 + ks * 8 + tig + 4];
            a[3] = m2[rr2 * 32 + ks * 8 + tig + 4];
            mma16816(c[0], a, Bl[ks][0]);
            mma16816(c[1], a, Bl[ks][1]);
        }
#pragma unroll
        for (int ks = 0; ks < 4; ++ks) {
            uint32_t a[4];
            a[0] = r2[rr1 * 32 + ks * 8 + tig];
            a[1] = r2[rr2 * 32 + ks * 8 + tig];
            a[2] = r2[rr1 * 32 + ks * 8 + tig + 4];
            a[3] = r2[rr2 * 32 + ks * 8 + tig + 4];
            mma16816(c[0], a, Br[ks][0]);
            mma16816(c[1], a, Br[ks][1]);
        }

        float inv1 = 1.0f, inv2 = 1.0f;
        if (NORM) {
            float s1 = c[0][0] * c[0][0] + c[0][1] * c[0][1]
                     + c[1][0] * c[1][0] + c[1][1] * c[1][1];
            float s2 = c[0][2] * c[0][2] + c[0][3] * c[0][3]
                     + c[1][2] * c[1][2] + c[1][3] * c[1][3];
            s1 += __shfl_xor_sync(~0u, s1, 1); s1 += __shfl_xor_sync(~0u, s1, 2);
            s2 += __shfl_xor_sync(~0u, s2, 1); s2 += __shfl_xor_sync(~0u, s2, 2);
            if (tig == 0) { ssq[pb][g][warp] = s1; ssq[pb][g + 8][warp] = s2; }
            __syncthreads();
            float4 q1 = *(const float4*)ssq[pb][g];
            float4 q2 = *(const float4*)ssq[pb][g + 8];
            inv1 = 1.0f / fmaxf(sqrtf(q1.x + q1.y + q1.z + q1.w), 1e-12f);
            inv2 = 1.0f / fmaxf(sqrtf(q2.x + q2.y + q2.z + q2.w), 1e-12f);
            pb ^= 1;
        }

#pragma unroll
        for (int nst = 0; nst < 2; ++nst) {
            int col = nbase + nst * 8 + 2 * tig;
            float o0 = c[nst][0] * inv1, o1 = c[nst][1] * inv1;
            float p0 = c[nst][2] * inv2, p1 = c[nst][3] * inv2;
            if (RELU) {
                o0 = fmaxf(o0, 0.0f); o1 = fmaxf(o1, 0.0f);
                p0 = fmaxf(p0, 0.0f); p1 = fmaxf(p1, 0.0f);
            }
            if (W16) {
                if (row1 < n)
                    ((__half2*)out16)[row1 * 32 + (col >> 1)] = __floats2half2_rn(o0, o1);
                if (row2 < n)
                    ((__half2*)out16)[row2 * 32 + (col >> 1)] = __floats2half2_rn(p0, p1);
            }
            if (WF32) {
                if (row1 < n && col < ocols) {
                    outf[(size_t)row1 * ostride + col] = o0;
                    if (col + 1 < ocols) outf[(size_t)row1 * ostride + col + 1] = o1;
                }
                if (row2 < n && col < ocols) {
                    outf[(size_t)row2 * ostride + col] = p0;
                    if (col + 1 < ocols) outf[(size_t)row2 * ostride + col + 1] = p1;
                }
            }
        }
    }
}

// ---------------- launch ---------------------------------------------------------
extern "C" void kernel_launch(void* const* d_in, const int* in_sizes, int n_in,
                              void* d_out, int out_size) {
    const float* x    = (const float*)d_in[0];
    const int*   ei   = (const int*)d_in[1];     // int32 [2, E]
    const float* ew   = (const float*)d_in[2];
    const float* embW = (const float*)d_in[3];
    const float* embB = (const float*)d_in[4];
    const float* Wl1 = (const float*)d_in[5];
    const float* bl1 = (const float*)d_in[6];
    const float* Wr1 = (const float*)d_in[7];
    const float* Wl2 = (const float*)d_in[8];
    const float* bl2 = (const float*)d_in[9];
    const float* Wr2 = (const float*)d_in[10];
    const float* Wl3 = (const float*)d_in[11];
    const float* bl3 = (const float*)d_in[12];
    const float* Wr3 = (const float*)d_in[13];
    const float* Wl4 = (const float*)d_in[14];
    const float* bl4 = (const float*)d_in[15];
    const float* Wr4 = (const float*)d_in[16];

    int n = in_sizes[0] / FIN;
    int e = in_sizes[2];

    __half *hA16, *hB16, *mv16;
    float *Wemb, *W4, *b4; int* cnt;
    cudaGetSymbolAddress((void**)&hA16, g_hA16);
    cudaGetSymbolAddress((void**)&hB16, g_hB16);
    cudaGetSymbolAddress((void**)&mv16, g_mv16);
    cudaGetSymbolAddress((void**)&Wemb, g_Wemb);
    cudaGetSymbolAddress((void**)&W4,   g_W4);
    cudaGetSymbolAddress((void**)&b4,   g_b4);
    cudaGetSymbolAddress((void**)&cnt,  g_cnt);

    cudaMemsetAsync(cnt, 0, (size_t)n * sizeof(int));

    // K1: convert | pad(+scan-slot reset) | hist
    int CB = (n * HD / 4 + 255) / 256;
    int HB = (e / 4 + 255) / 256;
    prep_kernel<<<CB + 32 + HB, 256>>>(x, embW, Wl4, bl4, Wr4, ei, n, e, CB);

    // K2: fused scan (single kernel, co-resident blocks)
    int nb = (n + 1023) / 1024;
    scan_fused_kernel<<<nb, 256>>>(n, nb);

    // K3: embed transform | fill
    const int TB = 1036;
    int FB = (e / 4 + 255) / 256;
    embed_fill_kernel<<<TB + FB, 256>>>(ei, ew, Wemb, embB, Wemb + HD * HD,
                                        hA16, n, e, TB);

    const int TG = 1480;
    int ggrid = (n + 7) / 8;
    gather_kernel<true><<<ggrid, 256>>>(hA16, mv16, n);
    transform_kernel<true, true, true, false><<<TG, 128>>>(
        mv16, hA16, Wl1, bl1, Wr1, nullptr, 0, 0, hB16, n);
    gather_kernel<true><<<ggrid, 256>>>(hB16, mv16, n);
    transform_kernel<true, true, true, false><<<TG, 128>>>(
        mv16, hB16, Wl2, bl2, Wr2, nullptr, 0, 0, hA16, n);
    gather_kernel<true><<<ggrid, 256>>>(hA16, mv16, n);
    transform_kernel<true, true, true, false><<<TG, 128>>>(
        mv16, hA16, Wl3, bl3, Wr3, nullptr, 0, 0, hB16, n);
    gather_kernel<false><<<ggrid, 256>>>(hB16, mv16, n);
    transform_kernel<false, true, false, true><<<TG, 128>>>(
        mv16, hB16, W4, b4, W4 + HD * HD, (float*)d_out, 18, 18, nullptr, n);
}

// round 15
// speedup vs baseline: 1.0605x; 1.0154x over previous
#include <cuda_runtime.h>
#include <cuda_fp16.h>
#include <cstdint>

#define FIN 100
#define HD  64
#define NMAX 100000
#define EMAX 3200000
#define NBMAX 128

// ---------------- scratch (device globals) -----------------------------------
__device__ __half g_hA16[NMAX * HD];
__device__ __half g_hB16[NMAX * HD];
__device__ __half g_mv16[NMAX * HD];
__device__ __half g_xlo16[NMAX * HD];
__device__ __half g_xhi16[NMAX * HD];
__device__ float  g_Wemb[2 * HD * HD];
__device__ float  g_W4[2 * HD * HD];
__device__ float  g_b4[HD];
__device__ int    g_cnt[NMAX];
__device__ int    g_rowstart[NMAX + 1];
__device__ int    g_cursor[NMAX];
__device__ int    g_scanpub[NBMAX];      // per-chunk sums, -1 = not ready
__device__ int2   g_edge[EMAX];

// ---------------- helpers ------------------------------------------------------
__device__ __forceinline__ uint32_t f2h2(float lo, float hi) {
    __half2 h = __floats2half2_rn(lo, hi);
    return *reinterpret_cast<uint32_t*>(&h);
}

__device__ __forceinline__ void mma16816(float c[4], const uint32_t a[4],
                                         const uint32_t b[2]) {
    asm volatile(
        "mma.sync.aligned.m16n8k16.row.col.f32.f16.f16.f32 "
        "{%0,%1,%2,%3}, {%4,%5,%6,%7}, {%8,%9}, {%0,%1,%2,%3};\n"
        : "+f"(c[0]), "+f"(c[1]), "+f"(c[2]), "+f"(c[3])
        : "r"(a[0]), "r"(a[1]), "r"(a[2]), "r"(a[3]), "r"(b[0]), "r"(b[1]));
}

__device__ __forceinline__ unsigned long long pack2f(float lo, float hi) {
    unsigned long long r;
    asm("mov.b64 %0, {%1, %2};" : "=l"(r) : "f"(lo), "f"(hi));
    return r;
}
__device__ __forceinline__ unsigned long long pack2u(uint32_t lo, uint32_t hi) {
    unsigned long long r;
    asm("mov.b64 %0, {%1, %2};" : "=l"(r) : "r"(lo), "r"(hi));
    return r;
}
__device__ __forceinline__ void ffma2(unsigned long long& acc,
                                      unsigned long long a,
                                      unsigned long long b) {
    asm("fma.rn.f32x2 %0, %1, %2, %0;" : "+l"(acc) : "l"(a), "l"(b));
}
__device__ __forceinline__ void unpack2f(float& lo, float& hi,
                                         unsigned long long v) {
    asm("mov.b64 {%0, %1}, %2;" : "=f"(lo), "=f"(hi) : "l"(v));
}

// ---------------- K1: convert_x | pad | hist (block-range roles) ---------------
__global__ void prep_kernel(const float* __restrict__ x,
                            const float* __restrict__ embW,
                            const float* __restrict__ Wl4,
                            const float* __restrict__ bl4,
                            const float* __restrict__ Wr4,
                            const int* __restrict__ ei,
                            int n, int e, int CB) {
    int bid = blockIdx.x;
    if (bid < CB) {
        int base = (bid * 256 + threadIdx.x) * 4;
        if (base >= n * HD) return;
        int node = base >> 6;
        int c    = base & 63;
        const float* xr = x + (size_t)node * FIN;
        float4 lo = *(const float4*)(xr + c);
        uint2 lo2 = make_uint2(f2h2(lo.x, lo.y), f2h2(lo.z, lo.w));
        *(uint2*)(g_xlo16 + base) = lo2;
        float4 hi = make_float4(0.f, 0.f, 0.f, 0.f);
        if (c < FIN - HD) hi = *(const float4*)(xr + HD + c);
        uint2 hi2 = make_uint2(f2h2(hi.x, hi.y), f2h2(hi.z, hi.w));
        *(uint2*)(g_xhi16 + base) = hi2;
    } else if (bid < CB + 32) {
        int tid = (bid - CB) * 256 + threadIdx.x;
        if (tid < NBMAX) g_scanpub[tid] = -1;    // reset scan publish slots
        if (tid < 2 * HD * HD) {
            int k = tid >> 6, c = tid & 63;
            g_Wemb[tid] = (k < FIN) ? embW[k * HD + c] : 0.0f;
        }
        if (tid < HD * HD) {
            int k = tid >> 6, c = tid & 63;
            g_W4[tid]           = (c < 18) ? Wl4[k * 18 + c] : 0.0f;
            g_W4[HD * HD + tid] = (c < 18) ? Wr4[k * 18 + c] : 0.0f;
        }
        if (tid < HD) g_b4[tid] = (tid < 18) ? bl4[tid] : 0.0f;
    } else {
        int base = ((bid - CB - 32) * 256 + threadIdx.x) * 4;
#pragma unroll
        for (int j = 0; j < 4; ++j) {
            int i = base + j;
            if (i < e) {
                int dst = ei[e + i];
                dst = min(max(dst, 0), n - 1);
                atomicAdd(&g_cnt[dst], 1);
            }
        }
    }
}

// ---------------- fused single-kernel scan --------------------------------------
__global__ void scan_fused_kernel(int n, int nb) {
    __shared__ int sw[8];
    __shared__ int sred[8];
    __shared__ int soff;
    int b    = blockIdx.x;
    int tid  = threadIdx.x;
    int lane = tid & 31;
    int warp = tid >> 5;
    int i0 = b * 1024 + tid * 4;
    int c[4];
    int ts = 0;
#pragma unroll
    for (int j = 0; j < 4; ++j) {
        int i = i0 + j;
        c[j] = (i < n) ? g_cnt[i] : 0;
        ts += c[j];
    }
    int x = ts;
#pragma unroll
    for (int o = 1; o < 32; o <<= 1) {
        int y = __shfl_up_sync(~0u, x, o);
        if (lane >= o) x += y;
    }
    if (lane == 31) sw[warp] = x;
    __syncthreads();
    if (tid < 8) {
        int y = sw[tid];
#pragma unroll
        for (int o = 1; o < 8; o <<= 1) {
            int z = __shfl_up_sync(0xFF, y, o);
            if (tid >= o) y += z;
        }
        sw[tid] = y;
    }
    __syncthreads();
    int total = sw[7];
    if (tid == 0) atomicExch(&g_scanpub[b], total);
    int pv = 0;
    if (tid < b) {
        int v;
        do { v = atomicAdd(&g_scanpub[tid], 0); } while (v < 0);
        pv = v;
    }
#pragma unroll
    for (int o = 16; o; o >>= 1) pv += __shfl_xor_sync(~0u, pv, o);
    if (lane == 0) sred[warp] = pv;
    __syncthreads();
    if (tid == 0) {
        int t = 0;
#pragma unroll
        for (int w = 0; w < 8; ++w) t += sred[w];
        soff = t;
    }
    __syncthreads();
    int offset = soff;
    int run = offset + (x - ts) + (warp > 0 ? sw[warp - 1] : 0);
#pragma unroll
    for (int j = 0; j < 4; ++j) {
        int i = i0 + j;
        if (i < n) {
            g_rowstart[i] = run;
            g_cursor[i]   = run;
        }
        run += c[j];
    }
    if (b == nb - 1 && tid == 0) g_rowstart[n] = offset + total;
}

// ---------------- K2: embed transform | fill (block-range roles) ---------------
__global__ void __launch_bounds__(256)
embed_fill_kernel(const int* __restrict__ ei, const float* __restrict__ w,
                  const float* __restrict__ Wl, const float* __restrict__ bl,
                  const float* __restrict__ Wr,
                  __half* __restrict__ out16, int n, int e, int TB) {
    int bid = blockIdx.x;
    if (bid >= TB) {   // ---- fill role ----
        int base = ((bid - TB) * 256 + threadIdx.x) * 4;
#pragma unroll
        for (int j = 0; j < 4; ++j) {
            int i = base + j;
            if (i < e) {
                int dst = ei[e + i];
                int src = ei[i];
                dst = min(max(dst, 0), n - 1);
                src = min(max(src, 0), n - 1);
                int pos = atomicAdd(&g_cursor[dst], 1);
                pos = min(max(pos, 0), EMAX - 1);
                g_edge[pos] = make_int2(src, __float_as_int(w[i]));
            }
        }
        return;
    }
    // ---- embed transform role ----
    int warp  = threadIdx.x >> 5;
    int lane  = threadIdx.x & 31;
    int g     = lane >> 2;
    int tig   = lane & 3;
    int sub   = warp & 3;
    int grp   = warp >> 2;
    int nbase = sub * 16;

    uint32_t Bl[4][2][2], Br[4][2][2];
#pragma unroll
    for (int ks = 0; ks < 4; ++ks)
#pragma unroll
        for (int nst = 0; nst < 2; ++nst) {
            int ncol = nbase + nst * 8 + g;
#pragma unroll
            for (int rr = 0; rr < 2; ++rr) {
                int k = ks * 16 + 2 * tig + rr * 8;
                Bl[ks][nst][rr] = f2h2(Wl[k * HD + ncol], Wl[(k + 1) * HD + ncol]);
                Br[ks][nst][rr] = f2h2(Wr[k * HD + ncol], Wr[(k + 1) * HD + ncol]);
            }
        }
    float bb[2][2];
#pragma unroll
    for (int nst = 0; nst < 2; ++nst) {
        bb[nst][0] = bl[nbase + nst * 8 + 2 * tig];
        bb[nst][1] = bl[nbase + nst * 8 + 2 * tig + 1];
    }

    const uint32_t* m2 = (const uint32_t*)g_xlo16;
    const uint32_t* r2 = (const uint32_t*)g_xhi16;
    int ntiles = (n + 15) >> 4;
    int npairs = (ntiles + 1) >> 1;

    for (int pr = bid; pr < npairs; pr += TB) {
        int tile = pr * 2 + grp;
        if (tile >= ntiles) continue;
        int row1 = tile * 16 + g;
        int row2 = row1 + 8;
        int rr1 = min(row1, n - 1);
        int rr2 = min(row2, n - 1);

        float c[2][4];
#pragma unroll
        for (int nst = 0; nst < 2; ++nst) {
            c[nst][0] = bb[nst][0]; c[nst][1] = bb[nst][1];
            c[nst][2] = bb[nst][0]; c[nst][3] = bb[nst][1];
        }
#pragma unroll
        for (int ks = 0; ks < 4; ++ks) {
            uint32_t a[4];
            a[0] = m2[rr1 * 32 + ks * 8 + tig];
            a[1] = m2[rr2 * 32 + ks * 8 + tig];
            a[2] = m2[rr1 * 32 + ks * 8 + tig + 4];
            a[3] = m2[rr2 * 32 + ks * 8 + tig + 4];
            mma16816(c[0], a, Bl[ks][0]);
            mma16816(c[1], a, Bl[ks][1]);
        }
#pragma unroll
        for (int ks = 0; ks < 4; ++ks) {
            uint32_t a[4];
            a[0] = r2[rr1 * 32 + ks * 8 + tig];
            a[1] = r2[rr2 * 32 + ks * 8 + tig];
            a[2] = r2[rr1 * 32 + ks * 8 + tig + 4];
            a[3] = r2[rr2 * 32 + ks * 8 + tig + 4];
            mma16816(c[0], a, Br[ks][0]);
            mma16816(c[1], a, Br[ks][1]);
        }
#pragma unroll
        for (int nst = 0; nst < 2; ++nst) {
            int col = nbase + nst * 8 + 2 * tig;
            float o0 = fmaxf(c[nst][0], 0.0f), o1 = fmaxf(c[nst][1], 0.0f);
            float p0 = fmaxf(c[nst][2], 0.0f), p1 = fmaxf(c[nst][3], 0.0f);
            if (row1 < n)
                ((__half2*)out16)[row1 * 32 + (col >> 1)] = __floats2half2_rn(o0, o1);
            if (row2 < n)
                ((__half2*)out16)[row2 * 32 + (col >> 1)] = __floats2half2_rn(p0, p1);
        }
    }
}

// ---------------- gather v6: LDG.128 + staged weights + f32x2 FMA + half-skip --
// Skip the second 16-edge half-chunk when mm <= 16: those slots are
// fma(0, v, acc) == acc exactly, so skipping is bit-identical and removes
// ~14% of all gather work (degree ~ Poisson(32) padding waste).
template <bool USE_W>
__global__ void __launch_bounds__(256)
gather_kernel(const __half* __restrict__ hin16,
              __half* __restrict__ mv16, int n) {
    __shared__ int2 sedge[8][32];
    int warp = threadIdx.x >> 5;
    int lane = threadIdx.x & 31;
    int g    = lane >> 3;
    int s    = lane & 7;
    int node = blockIdx.x * 8 + warp;
    if (node >= n) return;

    const uint4* h4 = (const uint4*)hin16;   // 8 uint4 per 64-col row
    int start = g_rowstart[node];
    int end   = g_rowstart[node + 1];

    unsigned long long acc64[4] = {0ull, 0ull, 0ull, 0ull};

    for (int i0 = start; i0 < end; i0 += 32) {
        int mm = min(32, end - i0);
        int2 eg = make_int2(0, 0);           // w = 0.0f for padding slots
        if (lane < mm) {
            eg = g_edge[i0 + lane];
            if (!USE_W) eg.y = 0x3f800000;   // w = 1.0f for valid slots
        }
        sedge[warp][lane] = eg;
        __syncwarp();

#pragma unroll
        for (int half = 0; half < 2; ++half) {
            if (half * 16 < mm) {            // uniform branch (mm warp-shared)
                int2  e[4];
                uint4 v[4];
#pragma unroll
                for (int j = 0; j < 4; ++j) e[j] = sedge[warp][(half * 4 + j) * 4 + g];
#pragma unroll
                for (int j = 0; j < 4; ++j) v[j] = h4[(size_t)e[j].x * 8 + s];
#pragma unroll
                for (int j = 0; j < 4; ++j) {
                    unsigned long long ww = pack2u((uint32_t)e[j].y, (uint32_t)e[j].y);
                    float2 f0 = __half22float2(*reinterpret_cast<__half2*>(&v[j].x));
                    float2 f1 = __half22float2(*reinterpret_cast<__half2*>(&v[j].y));
                    float2 f2 = __half22float2(*reinterpret_cast<__half2*>(&v[j].z));
                    float2 f3 = __half22float2(*reinterpret_cast<__half2*>(&v[j].w));
                    ffma2(acc64[0], pack2f(f0.x, f0.y), ww);
                    ffma2(acc64[1], pack2f(f1.x, f1.y), ww);
                    ffma2(acc64[2], pack2f(f2.x, f2.y), ww);
                    ffma2(acc64[3], pack2f(f3.x, f3.y), ww);
                }
            }
        }
        __syncwarp();
    }

    float acc[8];
#pragma unroll
    for (int k = 0; k < 4; ++k) unpack2f(acc[2 * k], acc[2 * k + 1], acc64[k]);

    // fold the 4 edge-groups (lanes with equal s)
#pragma unroll
    for (int k = 0; k < 8; ++k) {
        acc[k] += __shfl_xor_sync(~0u, acc[k], 8);
        acc[k] += __shfl_xor_sync(~0u, acc[k], 16);
    }
    float invd = 1.0f / fmaxf((float)(end - start), 1.0f);
    if (lane < 8) {
        uint4 o;
        o.x = f2h2(acc[0] * invd, acc[1] * invd);
        o.y = f2h2(acc[2] * invd, acc[3] * invd);
        o.z = f2h2(acc[4] * invd, acc[5] * invd);
        o.w = f2h2(acc[6] * invd, acc[7] * invd);
        ((uint4*)mv16)[(size_t)node * 8 + lane] = o;
    }
}

// ---------------- tensor transform (128 thr; ssq double-buffered) --------------
template <bool RELU, bool NORM, bool W16, bool WF32>
__global__ void __launch_bounds__(128)
transform_kernel(const __half* __restrict__ mv16,
                 const __half* __restrict__ root16,
                 const float* __restrict__ Wl,
                 const float* __restrict__ bl,
                 const float* __restrict__ Wr,
                 float* __restrict__ outf, int ostride, int ocols,
                 __half* __restrict__ out16, int n) {
    __shared__ __align__(16) float ssq[2][16][4];
    int warp = threadIdx.x >> 5;
    int lane = threadIdx.x & 31;
    int g    = lane >> 2;
    int tig  = lane & 3;
    int nbase = warp * 16;

    uint32_t Bl[4][2][2], Br[4][2][2];
#pragma unroll
    for (int ks = 0; ks < 4; ++ks)
#pragma unroll
        for (int nst = 0; nst < 2; ++nst) {
            int ncol = nbase + nst * 8 + g;
#pragma unroll
            for (int rr = 0; rr < 2; ++rr) {
                int k = ks * 16 + 2 * tig + rr * 8;
                Bl[ks][nst][rr] = f2h2(Wl[k * HD + ncol], Wl[(k + 1) * HD + ncol]);
                Br[ks][nst][rr] = f2h2(Wr[k * HD + ncol], Wr[(k + 1) * HD + ncol]);
            }
        }
    float bb[2][2];
#pragma unroll
    for (int nst = 0; nst < 2; ++nst) {
        bb[nst][0] = bl[nbase + nst * 8 + 2 * tig];
        bb[nst][1] = bl[nbase + nst * 8 + 2 * tig + 1];
    }

    const uint32_t* m2 = (const uint32_t*)mv16;
    const uint32_t* r2 = (const uint32_t*)root16;
    int ntiles = (n + 15) >> 4;
    int pb = 0;

    for (int tile = blockIdx.x; tile < ntiles; tile += gridDim.x) {
        int row1 = tile * 16 + g;
        int row2 = row1 + 8;
        int rr1 = min(row1, n - 1);
        int rr2 = min(row2, n - 1);

        float c[2][4];
#pragma unroll
        for (int nst = 0; nst < 2; ++nst) {
            c[nst][0] = bb[nst][0]; c[nst][1] = bb[nst][1];
            c[nst][2] = bb[nst][0]; c[nst][3] = bb[nst][1];
        }
#pragma unroll
        for (int ks = 0; ks < 4; ++ks) {
            uint32_t a[4];
            a[0] = m2[rr1 * 32 + ks * 8 + tig];
            a[1] = m2[rr2 * 32 + ks * 8 + tig];
            a[2] = m2[rr1 * 32 + ks * 8 + tig + 4];
            a[3] = m2[rr2 * 32 + ks * 8 + tig + 4];
            mma16816(c[0], a, Bl[ks][0]);
            mma16816(c[1], a, Bl[ks][1]);
        }
#pragma unroll
        for (int ks = 0; ks < 4; ++ks) {
            uint32_t a[4];
            a[0] = r2[rr1 * 32 + ks * 8 + tig];
            a[1] = r2[rr2 * 32 + ks * 8 + tig];
            a[2] = r2[rr1 * 32 + ks * 8 + tig + 4];
            a[3] = r2[rr2 * 32 + ks * 8 + tig + 4];
            mma16816(c[0], a, Br[ks][0]);
            mma16816(c[1], a, Br[ks][1]);
        }

        float inv1 = 1.0f, inv2 = 1.0f;
        if (NORM) {
            float s1 = c[0][0] * c[0][0] + c[0][1] * c[0][1]
                     + c[1][0] * c[1][0] + c[1][1] * c[1][1];
            float s2 = c[0][2] * c[0][2] + c[0][3] * c[0][3]
                     + c[1][2] * c[1][2] + c[1][3] * c[1][3];
            s1 += __shfl_xor_sync(~0u, s1, 1); s1 += __shfl_xor_sync(~0u, s1, 2);
            s2 += __shfl_xor_sync(~0u, s2, 1); s2 += __shfl_xor_sync(~0u, s2, 2);
            if (tig == 0) { ssq[pb][g][warp] = s1; ssq[pb][g + 8][warp] = s2; }
            __syncthreads();
            float4 q1 = *(const float4*)ssq[pb][g];
            float4 q2 = *(const float4*)ssq[pb][g + 8];
            inv1 = 1.0f / fmaxf(sqrtf(q1.x + q1.y + q1.z + q1.w), 1e-12f);
            inv2 = 1.0f / fmaxf(sqrtf(q2.x + q2.y + q2.z + q2.w), 1e-12f);
            pb ^= 1;
        }

#pragma unroll
        for (int nst = 0; nst < 2; ++nst) {
            int col = nbase + nst * 8 + 2 * tig;
            float o0 = c[nst][0] * inv1, o1 = c[nst][1] * inv1;
            float p0 = c[nst][2] * inv2, p1 = c[nst][3] * inv2;
            if (RELU) {
                o0 = fmaxf(o0, 0.0f); o1 = fmaxf(o1, 0.0f);
                p0 = fmaxf(p0, 0.0f); p1 = fmaxf(p1, 0.0f);
            }
            if (W16) {
                if (row1 < n)
                    ((__half2*)out16)[row1 * 32 + (col >> 1)] = __floats2half2_rn(o0, o1);
                if (row2 < n)
                    ((__half2*)out16)[row2 * 32 + (col >> 1)] = __floats2half2_rn(p0, p1);
            }
            if (WF32) {
                if (row1 < n && col < ocols) {
                    outf[(size_t)row1 * ostride + col] = o0;
                    if (col + 1 < ocols) outf[(size_t)row1 * ostride + col + 1] = o1;
                }
                if (row2 < n && col < ocols) {
                    outf[(size_t)row2 * ostride + col] = p0;
                    if (col + 1 < ocols) outf[(size_t)row2 * ostride + col + 1] = p1;
                }
            }
        }
    }
}

// ---------------- launch ---------------------------------------------------------
extern "C" void kernel_launch(void* const* d_in, const int* in_sizes, int n_in,
                              void* d_out, int out_size) {
    const float* x    = (const float*)d_in[0];
    const int*   ei   = (const int*)d_in[1];     // int32 [2, E]
    const float* ew   = (const float*)d_in[2];
    const float* embW = (const float*)d_in[3];
    const float* embB = (const float*)d_in[4];
    const float* Wl1 = (const float*)d_in[5];
    const float* bl1 = (const float*)d_in[6];
    const float* Wr1 = (const float*)d_in[7];
    const float* Wl2 = (const float*)d_in[8];
    const float* bl2 = (const float*)d_in[9];
    const float* Wr2 = (const float*)d_in[10];
    const float* Wl3 = (const float*)d_in[11];
    const float* bl3 = (const float*)d_in[12];
    const float* Wr3 = (const float*)d_in[13];
    const float* Wl4 = (const float*)d_in[14];
    const float* bl4 = (const float*)d_in[15];
    const float* Wr4 = (const float*)d_in[16];

    int n = in_sizes[0] / FIN;
    int e = in_sizes[2];

    __half *hA16, *hB16, *mv16;
    float *Wemb, *W4, *b4; int* cnt;
    cudaGetSymbolAddress((void**)&hA16, g_hA16);
    cudaGetSymbolAddress((void**)&hB16, g_hB16);
    cudaGetSymbolAddress((void**)&mv16, g_mv16);
    cudaGetSymbolAddress((void**)&Wemb, g_Wemb);
    cudaGetSymbolAddress((void**)&W4,   g_W4);
    cudaGetSymbolAddress((void**)&b4,   g_b4);
    cudaGetSymbolAddress((void**)&cnt,  g_cnt);

    cudaMemsetAsync(cnt, 0, (size_t)n * sizeof(int));

    // K1: convert | pad(+scan-slot reset) | hist
    int CB = (n * HD / 4 + 255) / 256;
    int HB = (e / 4 + 255) / 256;
    prep_kernel<<<CB + 32 + HB, 256>>>(x, embW, Wl4, bl4, Wr4, ei, n, e, CB);

    // K2: fused scan (single kernel, co-resident blocks)
    int nb = (n + 1023) / 1024;
    scan_fused_kernel<<<nb, 256>>>(n, nb);

    // K3: embed transform | fill
    const int TB = 1036;
    int FB = (e / 4 + 255) / 256;
    embed_fill_kernel<<<TB + FB, 256>>>(ei, ew, Wemb, embB, Wemb + HD * HD,
                                        hA16, n, e, TB);

    const int TG = 1480;
    int ggrid = (n + 7) / 8;
    gather_kernel<true><<<ggrid, 256>>>(hA16, mv16, n);
    transform_kernel<true, true, true, false><<<TG, 128>>>(
        mv16, hA16, Wl1, bl1, Wr1, nullptr, 0, 0, hB16, n);
    gather_kernel<true><<<ggrid, 256>>>(hB16, mv16, n);
    transform_kernel<true, true, true, false><<<TG, 128>>>(
        mv16, hB16, Wl2, bl2, Wr2, nullptr, 0, 0, hA16, n);
    gather_kernel<true><<<ggrid, 256>>>(hA16, mv16, n);
    transform_kernel<true, true, true, false><<<TG, 128>>>(
        mv16, hA16, Wl3, bl3, Wr3, nullptr, 0, 0, hB16, n);
    gather_kernel<false><<<ggrid, 256>>>(hB16, mv16, n);
    transform_kernel<false, true, false, true><<<TG, 128>>>(
        mv16, hB16, W4, b4, W4 + HD * HD, (float*)d_out, 18, 18, nullptr, n);
}

// round 16
// speedup vs baseline: 1.0718x; 1.0107x over previous
#include <cuda_runtime.h>
#include <cuda_fp16.h>
#include <cstdint>

#define FIN 100
#define HD  64
#define NMAX 100000
#define EMAX 3200000
#define CAPLOG 8
#define CAP (1 << CAPLOG)     // 256 slots per node bucket

// ---------------- scratch (device globals) -----------------------------------
__device__ __half g_hA16[NMAX * HD];
__device__ __half g_hB16[NMAX * HD];
__device__ __half g_mv16[NMAX * HD];
__device__ __half g_xlo16[NMAX * HD];
__device__ __half g_xhi16[NMAX * HD];
__device__ float  g_Wemb[2 * HD * HD];
__device__ float  g_W4[2 * HD * HD];
__device__ float  g_b4[HD];
__device__ int    g_cnt[NMAX];
__device__ int2   g_bucket[(size_t)NMAX * CAP];   // direct CSR buckets

// ---------------- helpers ------------------------------------------------------
__device__ __forceinline__ uint32_t f2h2(float lo, float hi) {
    __half2 h = __floats2half2_rn(lo, hi);
    return *reinterpret_cast<uint32_t*>(&h);
}

__device__ __forceinline__ void mma16816(float c[4], const uint32_t a[4],
                                         const uint32_t b[2]) {
    asm volatile(
        "mma.sync.aligned.m16n8k16.row.col.f32.f16.f16.f32 "
        "{%0,%1,%2,%3}, {%4,%5,%6,%7}, {%8,%9}, {%0,%1,%2,%3};\n"
        : "+f"(c[0]), "+f"(c[1]), "+f"(c[2]), "+f"(c[3])
        : "r"(a[0]), "r"(a[1]), "r"(a[2]), "r"(a[3]), "r"(b[0]), "r"(b[1]));
}

__device__ __forceinline__ unsigned long long pack2f(float lo, float hi) {
    unsigned long long r;
    asm("mov.b64 %0, {%1, %2};" : "=l"(r) : "f"(lo), "f"(hi));
    return r;
}
__device__ __forceinline__ unsigned long long pack2u(uint32_t lo, uint32_t hi) {
    unsigned long long r;
    asm("mov.b64 %0, {%1, %2};" : "=l"(r) : "r"(lo), "r"(hi));
    return r;
}
__device__ __forceinline__ void ffma2(unsigned long long& acc,
                                      unsigned long long a,
                                      unsigned long long b) {
    asm("fma.rn.f32x2 %0, %1, %2, %0;" : "+l"(acc) : "l"(a), "l"(b));
}
__device__ __forceinline__ void unpack2f(float& lo, float& hi,
                                         unsigned long long v) {
    asm("mov.b64 {%0, %1}, %2;" : "=f"(lo), "=f"(hi) : "l"(v));
}

// ---------------- K1: convert_x | pad | direct-fill (block-range roles) -------
__global__ void prep_kernel(const float* __restrict__ x,
                            const float* __restrict__ embW,
                            const float* __restrict__ Wl4,
                            const float* __restrict__ bl4,
                            const float* __restrict__ Wr4,
                            const int* __restrict__ ei,
                            const float* __restrict__ w,
                            int n, int e, int CB) {
    int bid = blockIdx.x;
    if (bid < CB) {
        int base = (bid * 256 + threadIdx.x) * 4;
        if (base >= n * HD) return;
        int node = base >> 6;
        int c    = base & 63;
        const float* xr = x + (size_t)node * FIN;
        float4 lo = *(const float4*)(xr + c);
        uint2 lo2 = make_uint2(f2h2(lo.x, lo.y), f2h2(lo.z, lo.w));
        *(uint2*)(g_xlo16 + base) = lo2;
        float4 hi = make_float4(0.f, 0.f, 0.f, 0.f);
        if (c < FIN - HD) hi = *(const float4*)(xr + HD + c);
        uint2 hi2 = make_uint2(f2h2(hi.x, hi.y), f2h2(hi.z, hi.w));
        *(uint2*)(g_xhi16 + base) = hi2;
    } else if (bid < CB + 32) {
        int tid = (bid - CB) * 256 + threadIdx.x;
        if (tid < 2 * HD * HD) {
            int k = tid >> 6, c = tid & 63;
            g_Wemb[tid] = (k < FIN) ? embW[k * HD + c] : 0.0f;
        }
        if (tid < HD * HD) {
            int k = tid >> 6, c = tid & 63;
            g_W4[tid]           = (c < 18) ? Wl4[k * 18 + c] : 0.0f;
            g_W4[HD * HD + tid] = (c < 18) ? Wr4[k * 18 + c] : 0.0f;
        }
        if (tid < HD) g_b4[tid] = (tid < 18) ? bl4[tid] : 0.0f;
    } else {
        // direct fill: one atomic + one 8B store per edge (no hist/scan passes)
        int base = ((bid - CB - 32) * 256 + threadIdx.x) * 4;
#pragma unroll
        for (int j = 0; j < 4; ++j) {
            int i = base + j;
            if (i < e) {
                int dst = ei[e + i];
                int src = ei[i];
                dst = min(max(dst, 0), n - 1);
                src = min(max(src, 0), n - 1);
                int pos = atomicAdd(&g_cnt[dst], 1);
                pos = min(pos, CAP - 1);     // safety clamp (never hit: max deg ~65)
                g_bucket[((size_t)dst << CAPLOG) + pos] =
                    make_int2(src, __float_as_int(w[i]));
            }
        }
    }
}

// ---------------- gather v7: bucket CSR + LDG.128 + f32x2 FMA + half-skip -----
// lane layout: g = lane>>3 picks edge group, s = lane&7 loads row bytes
// [16s,16s+16) as uint4. Weight bits staged in sedge (0.0 for padding ->
// exact no-op FMA); second 16-edge half skipped when mm <= 16.
template <bool USE_W>
__global__ void __launch_bounds__(256)
gather_kernel(const __half* __restrict__ hin16,
              __half* __restrict__ mv16, int n) {
    __shared__ int2 sedge[8][32];
    int warp = threadIdx.x >> 5;
    int lane = threadIdx.x & 31;
    int g    = lane >> 3;
    int s    = lane & 7;
    int node = blockIdx.x * 8 + warp;
    if (node >= n) return;

    const uint4* h4 = (const uint4*)hin16;   // 8 uint4 per 64-col row
    int deg = min(g_cnt[node], CAP);
    const int2* bucket = g_bucket + ((size_t)node << CAPLOG);

    unsigned long long acc64[4] = {0ull, 0ull, 0ull, 0ull};

    for (int i0 = 0; i0 < deg; i0 += 32) {
        int mm = min(32, deg - i0);
        int2 eg = make_int2(0, 0);           // w = 0.0f for padding slots
        if (lane < mm) {
            eg = bucket[i0 + lane];
            if (!USE_W) eg.y = 0x3f800000;   // w = 1.0f for valid slots
        }
        sedge[warp][lane] = eg;
        __syncwarp();

#pragma unroll
        for (int half = 0; half < 2; ++half) {
            if (half * 16 < mm) {            // uniform branch (mm warp-shared)
                int2  e[4];
                uint4 v[4];
#pragma unroll
                for (int j = 0; j < 4; ++j) e[j] = sedge[warp][(half * 4 + j) * 4 + g];
#pragma unroll
                for (int j = 0; j < 4; ++j) v[j] = h4[(size_t)e[j].x * 8 + s];
#pragma unroll
                for (int j = 0; j < 4; ++j) {
                    unsigned long long ww = pack2u((uint32_t)e[j].y, (uint32_t)e[j].y);
                    float2 f0 = __half22float2(*reinterpret_cast<__half2*>(&v[j].x));
                    float2 f1 = __half22float2(*reinterpret_cast<__half2*>(&v[j].y));
                    float2 f2 = __half22float2(*reinterpret_cast<__half2*>(&v[j].z));
                    float2 f3 = __half22float2(*reinterpret_cast<__half2*>(&v[j].w));
                    ffma2(acc64[0], pack2f(f0.x, f0.y), ww);
                    ffma2(acc64[1], pack2f(f1.x, f1.y), ww);
                    ffma2(acc64[2], pack2f(f2.x, f2.y), ww);
                    ffma2(acc64[3], pack2f(f3.x, f3.y), ww);
                }
            }
        }
        __syncwarp();
    }

    float acc[8];
#pragma unroll
    for (int k = 0; k < 4; ++k) unpack2f(acc[2 * k], acc[2 * k + 1], acc64[k]);

    // fold the 4 edge-groups (lanes with equal s)
#pragma unroll
    for (int k = 0; k < 8; ++k) {
        acc[k] += __shfl_xor_sync(~0u, acc[k], 8);
        acc[k] += __shfl_xor_sync(~0u, acc[k], 16);
    }
    float invd = 1.0f / fmaxf((float)deg, 1.0f);
    if (lane < 8) {
        uint4 o;
        o.x = f2h2(acc[0] * invd, acc[1] * invd);
        o.y = f2h2(acc[2] * invd, acc[3] * invd);
        o.z = f2h2(acc[4] * invd, acc[5] * invd);
        o.w = f2h2(acc[6] * invd, acc[7] * invd);
        ((uint4*)mv16)[(size_t)node * 8 + lane] = o;
    }
}

// ---------------- tensor transform (128 thr; ssq double-buffered) --------------
template <bool RELU, bool NORM, bool W16, bool WF32>
__global__ void __launch_bounds__(128)
transform_kernel(const __half* __restrict__ mv16,
                 const __half* __restrict__ root16,
                 const float* __restrict__ Wl,
                 const float* __restrict__ bl,
                 const float* __restrict__ Wr,
                 float* __restrict__ outf, int ostride, int ocols,
                 __half* __restrict__ out16, int n) {
    __shared__ __align__(16) float ssq[2][16][4];
    int warp = threadIdx.x >> 5;
    int lane = threadIdx.x & 31;
    int g    = lane >> 2;
    int tig  = lane & 3;
    int nbase = warp * 16;

    uint32_t Bl[4][2][2], Br[4][2][2];
#pragma unroll
    for (int ks = 0; ks < 4; ++ks)
#pragma unroll
        for (int nst = 0; nst < 2; ++nst) {
            int ncol = nbase + nst * 8 + g;
#pragma unroll
            for (int rr = 0; rr < 2; ++rr) {
                int k = ks * 16 + 2 * tig + rr * 8;
                Bl[ks][nst][rr] = f2h2(Wl[k * HD + ncol], Wl[(k + 1) * HD + ncol]);
                Br[ks][nst][rr] = f2h2(Wr[k * HD + ncol], Wr[(k + 1) * HD + ncol]);
            }
        }
    float bb[2][2];
#pragma unroll
    for (int nst = 0; nst < 2; ++nst) {
        bb[nst][0] = bl[nbase + nst * 8 + 2 * tig];
        bb[nst][1] = bl[nbase + nst * 8 + 2 * tig + 1];
    }

    const uint32_t* m2 = (const uint32_t*)mv16;
    const uint32_t* r2 = (const uint32_t*)root16;
    int ntiles = (n + 15) >> 4;
    int pb = 0;

    for (int tile = blockIdx.x; tile < ntiles; tile += gridDim.x) {
        int row1 = tile * 16 + g;
        int row2 = row1 + 8;
        int rr1 = min(row1, n - 1);
        int rr2 = min(row2, n - 1);

        float c[2][4];
#pragma unroll
        for (int nst = 0; nst < 2; ++nst) {
            c[nst][0] = bb[nst][0]; c[nst][1] = bb[nst][1];
            c[nst][2] = bb[nst][0]; c[nst][3] = bb[nst][1];
        }
#pragma unroll
        for (int ks = 0; ks < 4; ++ks) {
            uint32_t a[4];
            a[0] = m2[rr1 * 32 + ks * 8 + tig];
            a[1] = m2[rr2 * 32 + ks * 8 + tig];
            a[2] = m2[rr1 * 32 + ks * 8 + tig + 4];
            a[3] = m2[rr2 * 32 + ks * 8 + tig + 4];
            mma16816(c[0], a, Bl[ks][0]);
            mma16816(c[1], a, Bl[ks][1]);
        }
#pragma unroll
        for (int ks = 0; ks < 4; ++ks) {
            uint32_t a[4];
            a[0] = r2[rr1 * 32 + ks * 8 + tig];
            a[1] = r2[rr2 * 32 + ks * 8 + tig];
            a[2] = r2[rr1 * 32 + ks * 8 + tig + 4];
            a[3] = r2[rr2 * 32 + ks * 8 + tig + 4];
            mma16816(c[0], a, Br[ks][0]);
            mma16816(c[1], a, Br[ks][1]);
        }

        float inv1 = 1.0f, inv2 = 1.0f;
        if (NORM) {
            float s1 = c[0][0] * c[0][0] + c[0][1] * c[0][1]
                     + c[1][0] * c[1][0] + c[1][1] * c[1][1];
            float s2 = c[0][2] * c[0][2] + c[0][3] * c[0][3]
                     + c[1][2] * c[1][2] + c[1][3] * c[1][3];
            s1 += __shfl_xor_sync(~0u, s1, 1); s1 += __shfl_xor_sync(~0u, s1, 2);
            s2 += __shfl_xor_sync(~0u, s2, 1); s2 += __shfl_xor_sync(~0u, s2, 2);
            if (tig == 0) { ssq[pb][g][warp] = s1; ssq[pb][g + 8][warp] = s2; }
            __syncthreads();
            float4 q1 = *(const float4*)ssq[pb][g];
            float4 q2 = *(const float4*)ssq[pb][g + 8];
            inv1 = 1.0f / fmaxf(sqrtf(q1.x + q1.y + q1.z + q1.w), 1e-12f);
            inv2 = 1.0f / fmaxf(sqrtf(q2.x + q2.y + q2.z + q2.w), 1e-12f);
            pb ^= 1;
        }

#pragma unroll
        for (int nst = 0; nst < 2; ++nst) {
            int col = nbase + nst * 8 + 2 * tig;
            float o0 = c[nst][0] * inv1, o1 = c[nst][1] * inv1;
            float p0 = c[nst][2] * inv2, p1 = c[nst][3] * inv2;
            if (RELU) {
                o0 = fmaxf(o0, 0.0f); o1 = fmaxf(o1, 0.0f);
                p0 = fmaxf(p0, 0.0f); p1 = fmaxf(p1, 0.0f);
            }
            if (W16) {
                if (row1 < n)
                    ((__half2*)out16)[row1 * 32 + (col >> 1)] = __floats2half2_rn(o0, o1);
                if (row2 < n)
                    ((__half2*)out16)[row2 * 32 + (col >> 1)] = __floats2half2_rn(p0, p1);
            }
            if (WF32) {
                if (row1 < n && col < ocols) {
                    outf[(size_t)row1 * ostride + col] = o0;
                    if (col + 1 < ocols) outf[(size_t)row1 * ostride + col + 1] = o1;
                }
                if (row2 < n && col < ocols) {
                    outf[(size_t)row2 * ostride + col] = p0;
                    if (col + 1 < ocols) outf[(size_t)row2 * ostride + col + 1] = p1;
                }
            }
        }
    }
}

// ---------------- launch ---------------------------------------------------------
extern "C" void kernel_launch(void* const* d_in, const int* in_sizes, int n_in,
                              void* d_out, int out_size) {
    const float* x    = (const float*)d_in[0];
    const int*   ei   = (const int*)d_in[1];     // int32 [2, E]
    const float* ew   = (const float*)d_in[2];
    const float* embW = (const float*)d_in[3];
    const float* embB = (const float*)d_in[4];
    const float* Wl1 = (const float*)d_in[5];
    const float* bl1 = (const float*)d_in[6];
    const float* Wr1 = (const float*)d_in[7];
    const float* Wl2 = (const float*)d_in[8];
    const float* bl2 = (const float*)d_in[9];
    const float* Wr2 = (const float*)d_in[10];
    const float* Wl3 = (const float*)d_in[11];
    const float* bl3 = (const float*)d_in[12];
    const float* Wr3 = (const float*)d_in[13];
    const float* Wl4 = (const float*)d_in[14];
    const float* bl4 = (const float*)d_in[15];
    const float* Wr4 = (const float*)d_in[16];

    int n = in_sizes[0] / FIN;
    int e = in_sizes[2];

    __half *hA16, *hB16, *mv16, *xlo, *xhi;
    float *Wemb, *W4, *b4; int* cnt;
    cudaGetSymbolAddress((void**)&hA16, g_hA16);
    cudaGetSymbolAddress((void**)&hB16, g_hB16);
    cudaGetSymbolAddress((void**)&mv16, g_mv16);
    cudaGetSymbolAddress((void**)&xlo,  g_xlo16);
    cudaGetSymbolAddress((void**)&xhi,  g_xhi16);
    cudaGetSymbolAddress((void**)&Wemb, g_Wemb);
    cudaGetSymbolAddress((void**)&W4,   g_W4);
    cudaGetSymbolAddress((void**)&b4,   g_b4);
    cudaGetSymbolAddress((void**)&cnt,  g_cnt);

    cudaMemsetAsync(cnt, 0, (size_t)n * sizeof(int));

    // K1: convert | pad | direct-fill (hist + scan eliminated)
    int CB = (n * HD / 4 + 255) / 256;
    int FB = (e / 4 + 255) / 256;
    prep_kernel<<<CB + 32 + FB, 256>>>(x, embW, Wl4, bl4, Wr4, ei, ew, n, e, CB);

    const int TG = 1480;
    // K2: embed transform (GEMM on xlo|xhi)
    transform_kernel<true, false, true, false><<<TG, 128>>>(
        xlo, xhi, Wemb, embB, Wemb + HD * HD, nullptr, 0, 0, hA16, n);

    int ggrid = (n + 7) / 8;
    gather_kernel<true><<<ggrid, 256>>>(hA16, mv16, n);
    transform_kernel<true, true, true, false><<<TG, 128>>>(
        mv16, hA16, Wl1, bl1, Wr1, nullptr, 0, 0, hB16, n);
    gather_kernel<true><<<ggrid, 256>>>(hB16, mv16, n);
    transform_kernel<true, true, true, false><<<TG, 128>>>(
        mv16, hB16, Wl2, bl2, Wr2, nullptr, 0, 0, hA16, n);
    gather_kernel<true><<<ggrid, 256>>>(hA16, mv16, n);
    transform_kernel<true, true, true, false><<<TG, 128>>>(
        mv16, hA16, Wl3, bl3, Wr3, nullptr, 0, 0, hB16, n);
    gather_kernel<false><<<ggrid, 256>>>(hB16, mv16, n);
    transform_kernel<false, true, false, true><<<TG, 128>>>(
        mv16, hB16, W4, b4, W4 + HD * HD, (float*)d_out, 18, 18, nullptr, n);
}

// round 17
// speedup vs baseline: 1.3647x; 1.2733x over previous
#include <cuda_runtime.h>
#include <cuda_fp16.h>
#include <cstdint>

#define FIN 100
#define HD  64
#define NMAX 100000
#define EMAX 3200000
#define CAPLOG 8
#define CAP (1 << CAPLOG)     // 256 slots per node bucket

// ---------------- scratch (device globals) -----------------------------------
__device__ __half g_hA16[NMAX * HD];
__device__ __half g_hB16[NMAX * HD];
__device__ __half g_mv16[NMAX * HD];
__device__ __half g_xlo16[NMAX * HD];
__device__ __half g_xhi16[NMAX * HD];
__device__ float  g_Wemb[2 * HD * HD];
__device__ float  g_W4[2 * HD * HD];
__device__ float  g_b4[HD];
__device__ int    g_cnt[NMAX];
__device__ int2   g_bucket[(size_t)NMAX * CAP];   // direct CSR buckets

// ---------------- helpers ------------------------------------------------------
__device__ __forceinline__ uint32_t f2h2(float lo, float hi) {
    __half2 h = __floats2half2_rn(lo, hi);
    return *reinterpret_cast<uint32_t*>(&h);
}

__device__ __forceinline__ void mma16816(float c[4], const uint32_t a[4],
                                         const uint32_t b[2]) {
    asm volatile(
        "mma.sync.aligned.m16n8k16.row.col.f32.f16.f16.f32 "
        "{%0,%1,%2,%3}, {%4,%5,%6,%7}, {%8,%9}, {%0,%1,%2,%3};\n"
        : "+f"(c[0]), "+f"(c[1]), "+f"(c[2]), "+f"(c[3])
        : "r"(a[0]), "r"(a[1]), "r"(a[2]), "r"(a[3]), "r"(b[0]), "r"(b[1]));
}

__device__ __forceinline__ void ldmatrix_x4(uint32_t a[4], uint32_t saddr) {
    asm volatile(
        "ldmatrix.sync.aligned.m8n8.x4.shared.b16 {%0,%1,%2,%3}, [%4];"
        : "=r"(a[0]), "=r"(a[1]), "=r"(a[2]), "=r"(a[3]) : "r"(saddr));
}

__device__ __forceinline__ unsigned long long pack2f(float lo, float hi) {
    unsigned long long r;
    asm("mov.b64 %0, {%1, %2};" : "=l"(r) : "f"(lo), "f"(hi));
    return r;
}
__device__ __forceinline__ unsigned long long pack2u(uint32_t lo, uint32_t hi) {
    unsigned long long r;
    asm("mov.b64 %0, {%1, %2};" : "=l"(r) : "r"(lo), "r"(hi));
    return r;
}
__device__ __forceinline__ void ffma2(unsigned long long& acc,
                                      unsigned long long a,
                                      unsigned long long b) {
    asm("fma.rn.f32x2 %0, %1, %2, %0;" : "+l"(acc) : "l"(a), "l"(b));
}
__device__ __forceinline__ void unpack2f(float& lo, float& hi,
                                         unsigned long long v) {
    asm("mov.b64 {%0, %1}, %2;" : "=f"(lo), "=f"(hi) : "l"(v));
}

// ---------------- K1: convert_x | pad | direct-fill (block-range roles) -------
__global__ void prep_kernel(const float* __restrict__ x,
                            const float* __restrict__ embW,
                            const float* __restrict__ Wl4,
                            const float* __restrict__ bl4,
                            const float* __restrict__ Wr4,
                            const int* __restrict__ ei,
                            const float* __restrict__ w,
                            int n, int e, int CB) {
    int bid = blockIdx.x;
    if (bid < CB) {
        int base = (bid * 256 + threadIdx.x) * 4;
        if (base >= n * HD) return;
        int node = base >> 6;
        int c    = base & 63;
        const float* xr = x + (size_t)node * FIN;
        float4 lo = *(const float4*)(xr + c);
        uint2 lo2 = make_uint2(f2h2(lo.x, lo.y), f2h2(lo.z, lo.w));
        *(uint2*)(g_xlo16 + base) = lo2;
        float4 hi = make_float4(0.f, 0.f, 0.f, 0.f);
        if (c < FIN - HD) hi = *(const float4*)(xr + HD + c);
        uint2 hi2 = make_uint2(f2h2(hi.x, hi.y), f2h2(hi.z, hi.w));
        *(uint2*)(g_xhi16 + base) = hi2;
    } else if (bid < CB + 32) {
        int tid = (bid - CB) * 256 + threadIdx.x;
        if (tid < 2 * HD * HD) {
            int k = tid >> 6, c = tid & 63;
            g_Wemb[tid] = (k < FIN) ? embW[k * HD + c] : 0.0f;
        }
        if (tid < HD * HD) {
            int k = tid >> 6, c = tid & 63;
            g_W4[tid]           = (c < 18) ? Wl4[k * 18 + c] : 0.0f;
            g_W4[HD * HD + tid] = (c < 18) ? Wr4[k * 18 + c] : 0.0f;
        }
        if (tid < HD) g_b4[tid] = (tid < 18) ? bl4[tid] : 0.0f;
    } else {
        // direct fill: one atomic + one 8B store per edge (no hist/scan passes)
        int base = ((bid - CB - 32) * 256 + threadIdx.x) * 4;
#pragma unroll
        for (int j = 0; j < 4; ++j) {
            int i = base + j;
            if (i < e) {
                int dst = ei[e + i];
                int src = ei[i];
                dst = min(max(dst, 0), n - 1);
                src = min(max(src, 0), n - 1);
                int pos = atomicAdd(&g_cnt[dst], 1);
                pos = min(pos, CAP - 1);
                g_bucket[((size_t)dst << CAPLOG) + pos] =
                    make_int2(src, __float_as_int(w[i]));
            }
        }
    }
}

// ---------------- gather v7: bucket CSR + LDG.128 + f32x2 FMA + half-skip -----
template <bool USE_W>
__global__ void __launch_bounds__(256)
gather_kernel(const __half* __restrict__ hin16,
              __half* __restrict__ mv16, int n) {
    __shared__ int2 sedge[8][32];
    int warp = threadIdx.x >> 5;
    int lane = threadIdx.x & 31;
    int g    = lane >> 3;
    int s    = lane & 7;
    int node = blockIdx.x * 8 + warp;
    if (node >= n) return;

    const uint4* h4 = (const uint4*)hin16;   // 8 uint4 per 64-col row
    int deg = min(g_cnt[node], CAP);
    const int2* bucket = g_bucket + ((size_t)node << CAPLOG);

    unsigned long long acc64[4] = {0ull, 0ull, 0ull, 0ull};

    for (int i0 = 0; i0 < deg; i0 += 32) {
        int mm = min(32, deg - i0);
        int2 eg = make_int2(0, 0);           // w = 0.0f for padding slots
        if (lane < mm) {
            eg = bucket[i0 + lane];
            if (!USE_W) eg.y = 0x3f800000;   // w = 1.0f for valid slots
        }
        sedge[warp][lane] = eg;
        __syncwarp();

#pragma unroll
        for (int half = 0; half < 2; ++half) {
            if (half * 16 < mm) {            // uniform branch (mm warp-shared)
                int2  e[4];
                uint4 v[4];
#pragma unroll
                for (int j = 0; j < 4; ++j) e[j] = sedge[warp][(half * 4 + j) * 4 + g];
#pragma unroll
                for (int j = 0; j < 4; ++j) v[j] = h4[(size_t)e[j].x * 8 + s];
#pragma unroll
                for (int j = 0; j < 4; ++j) {
                    unsigned long long ww = pack2u((uint32_t)e[j].y, (uint32_t)e[j].y);
                    float2 f0 = __half22float2(*reinterpret_cast<__half2*>(&v[j].x));
                    float2 f1 = __half22float2(*reinterpret_cast<__half2*>(&v[j].y));
                    float2 f2 = __half22float2(*reinterpret_cast<__half2*>(&v[j].z));
                    float2 f3 = __half22float2(*reinterpret_cast<__half2*>(&v[j].w));
                    ffma2(acc64[0], pack2f(f0.x, f0.y), ww);
                    ffma2(acc64[1], pack2f(f1.x, f1.y), ww);
                    ffma2(acc64[2], pack2f(f2.x, f2.y), ww);
                    ffma2(acc64[3], pack2f(f3.x, f3.y), ww);
                }
            }
        }
        __syncwarp();
    }

    float acc[8];
#pragma unroll
    for (int k = 0; k < 4; ++k) unpack2f(acc[2 * k], acc[2 * k + 1], acc64[k]);

#pragma unroll
    for (int k = 0; k < 8; ++k) {
        acc[k] += __shfl_xor_sync(~0u, acc[k], 8);
        acc[k] += __shfl_xor_sync(~0u, acc[k], 16);
    }
    float invd = 1.0f / fmaxf((float)deg, 1.0f);
    if (lane < 8) {
        uint4 o;
        o.x = f2h2(acc[0] * invd, acc[1] * invd);
        o.y = f2h2(acc[2] * invd, acc[3] * invd);
        o.z = f2h2(acc[4] * invd, acc[5] * invd);
        o.w = f2h2(acc[6] * invd, acc[7] * invd);
        ((uint4*)mv16)[(size_t)node * 8 + lane] = o;
    }
}

// ---------------- tensor transform v2: smem-staged A + ldmatrix ---------------
// Per tile: block stages 16-row mean & root slabs (coalesced uint4), then
// fragments come from smem via ldmatrix.x4 (row stride 144B: conflict-free
// for both STS.128 staging and LDSM). Double-buffered slabs -> 1 barrier/tile.
#define ROWB 144   // 16B-aligned padded row stride (36 words)

template <bool RELU, bool NORM, bool W16, bool WF32>
__global__ void __launch_bounds__(128)
transform_kernel(const __half* __restrict__ mv16,
                 const __half* __restrict__ root16,
                 const float* __restrict__ Wl,
                 const float* __restrict__ bl,
                 const float* __restrict__ Wr,
                 float* __restrict__ outf, int ostride, int ocols,
                 __half* __restrict__ out16, int n) {
    __shared__ __align__(16) unsigned char sA[2][16 * ROWB];
    __shared__ __align__(16) unsigned char sR[2][16 * ROWB];
    __shared__ __align__(16) float ssq[2][16][4];

    int tid  = threadIdx.x;
    int warp = tid >> 5;
    int lane = tid & 31;
    int g    = lane >> 2;
    int tig  = lane & 3;
    int nbase = warp * 16;

    // --- B fragments + bias, once per kernel ---
    uint32_t Bl[4][2][2], Br[4][2][2];
#pragma unroll
    for (int ks = 0; ks < 4; ++ks)
#pragma unroll
        for (int nst = 0; nst < 2; ++nst) {
            int ncol = nbase + nst * 8 + g;
#pragma unroll
            for (int rr = 0; rr < 2; ++rr) {
                int k = ks * 16 + 2 * tig + rr * 8;
                Bl[ks][nst][rr] = f2h2(Wl[k * HD + ncol], Wl[(k + 1) * HD + ncol]);
                Br[ks][nst][rr] = f2h2(Wr[k * HD + ncol], Wr[(k + 1) * HD + ncol]);
            }
        }
    float bb[2][2];
#pragma unroll
    for (int nst = 0; nst < 2; ++nst) {
        bb[nst][0] = bl[nbase + nst * 8 + 2 * tig];
        bb[nst][1] = bl[nbase + nst * 8 + 2 * tig + 1];
    }

    const uint4* m4 = (const uint4*)mv16;
    const uint4* r4 = (const uint4*)root16;
    int srow = tid >> 3;          // staging row 0..15
    int sseg = tid & 7;           // staging 16B segment 0..7

    // ldmatrix per-lane base offsets (row = lane&15, col half = lane>>4)
    uint32_t aB[2], rB[2];
#pragma unroll
    for (int p = 0; p < 2; ++p) {
        aB[p] = (uint32_t)__cvta_generic_to_shared(sA[p])
                + (lane & 15) * ROWB + (lane >> 4) * 16;
        rB[p] = (uint32_t)__cvta_generic_to_shared(sR[p])
                + (lane & 15) * ROWB + (lane >> 4) * 16;
    }

    int ntiles = (n + 15) >> 4;
    int pb = 0;

    for (int tile = blockIdx.x; tile < ntiles; tile += gridDim.x) {
        // ---- stage slabs (coalesced) ----
        int rs = min(tile * 16 + srow, n - 1);
        *(uint4*)(sA[pb] + srow * ROWB + sseg * 16) = m4[(size_t)rs * 8 + sseg];
        *(uint4*)(sR[pb] + srow * ROWB + sseg * 16) = r4[(size_t)rs * 8 + sseg];
        __syncthreads();

        int row1 = tile * 16 + g;
        int row2 = row1 + 8;

        float c[2][4];
#pragma unroll
        for (int nst = 0; nst < 2; ++nst) {
            c[nst][0] = bb[nst][0]; c[nst][1] = bb[nst][1];
            c[nst][2] = bb[nst][0]; c[nst][3] = bb[nst][1];
        }
#pragma unroll
        for (int ks = 0; ks < 4; ++ks) {
            uint32_t a[4];
            ldmatrix_x4(a, aB[pb] + ks * 32);
            mma16816(c[0], a, Bl[ks][0]);
            mma16816(c[1], a, Bl[ks][1]);
        }
#pragma unroll
        for (int ks = 0; ks < 4; ++ks) {
            uint32_t a[4];
            ldmatrix_x4(a, rB[pb] + ks * 32);
            mma16816(c[0], a, Br[ks][0]);
            mma16816(c[1], a, Br[ks][1]);
        }

        float inv1 = 1.0f, inv2 = 1.0f;
        if (NORM) {
            float s1 = c[0][0] * c[0][0] + c[0][1] * c[0][1]
                     + c[1][0] * c[1][0] + c[1][1] * c[1][1];
            float s2 = c[0][2] * c[0][2] + c[0][3] * c[0][3]
                     + c[1][2] * c[1][2] + c[1][3] * c[1][3];
            s1 += __shfl_xor_sync(~0u, s1, 1); s1 += __shfl_xor_sync(~0u, s1, 2);
            s2 += __shfl_xor_sync(~0u, s2, 1); s2 += __shfl_xor_sync(~0u, s2, 2);
            if (tig == 0) { ssq[pb][g][warp] = s1; ssq[pb][g + 8][warp] = s2; }
            __syncthreads();
            float4 q1 = *(const float4*)ssq[pb][g];
            float4 q2 = *(const float4*)ssq[pb][g + 8];
            inv1 = 1.0f / fmaxf(sqrtf(q1.x + q1.y + q1.z + q1.w), 1e-12f);
            inv2 = 1.0f / fmaxf(sqrtf(q2.x + q2.y + q2.z + q2.w), 1e-12f);
        }

#pragma unroll
        for (int nst = 0; nst < 2; ++nst) {
            int col = nbase + nst * 8 + 2 * tig;
            float o0 = c[nst][0] * inv1, o1 = c[nst][1] * inv1;
            float p0 = c[nst][2] * inv2, p1 = c[nst][3] * inv2;
            if (RELU) {
                o0 = fmaxf(o0, 0.0f); o1 = fmaxf(o1, 0.0f);
                p0 = fmaxf(p0, 0.0f); p1 = fmaxf(p1, 0.0f);
            }
            if (W16) {
                if (row1 < n)
                    ((__half2*)out16)[row1 * 32 + (col >> 1)] = __floats2half2_rn(o0, o1);
                if (row2 < n)
                    ((__half2*)out16)[row2 * 32 + (col >> 1)] = __floats2half2_rn(p0, p1);
            }
            if (WF32) {
                if (row1 < n && col < ocols) {
                    outf[(size_t)row1 * ostride + col] = o0;
                    if (col + 1 < ocols) outf[(size_t)row1 * ostride + col + 1] = o1;
                }
                if (row2 < n && col < ocols) {
                    outf[(size_t)row2 * ostride + col] = p0;
                    if (col + 1 < ocols) outf[(size_t)row2 * ostride + col + 1] = p1;
                }
            }
        }
        pb ^= 1;   // double-buffered slabs/ssq: no trailing barrier
    }
}

// ---------------- launch ---------------------------------------------------------
extern "C" void kernel_launch(void* const* d_in, const int* in_sizes, int n_in,
                              void* d_out, int out_size) {
    const float* x    = (const float*)d_in[0];
    const int*   ei   = (const int*)d_in[1];     // int32 [2, E]
    const float* ew   = (const float*)d_in[2];
    const float* embW = (const float*)d_in[3];
    const float* embB = (const float*)d_in[4];
    const float* Wl1 = (const float*)d_in[5];
    const float* bl1 = (const float*)d_in[6];
    const float* Wr1 = (const float*)d_in[7];
    const float* Wl2 = (const float*)d_in[8];
    const float* bl2 = (const float*)d_in[9];
    const float* Wr2 = (const float*)d_in[10];
    const float* Wl3 = (const float*)d_in[11];
    const float* bl3 = (const float*)d_in[12];
    const float* Wr3 = (const float*)d_in[13];
    const float* Wl4 = (const float*)d_in[14];
    const float* bl4 = (const float*)d_in[15];
    const float* Wr4 = (const float*)d_in[16];

    int n = in_sizes[0] / FIN;
    int e = in_sizes[2];

    __half *hA16, *hB16, *mv16, *xlo, *xhi;
    float *Wemb, *W4, *b4; int* cnt;
    cudaGetSymbolAddress((void**)&hA16, g_hA16);
    cudaGetSymbolAddress((void**)&hB16, g_hB16);
    cudaGetSymbolAddress((void**)&mv16, g_mv16);
    cudaGetSymbolAddress((void**)&xlo,  g_xlo16);
    cudaGetSymbolAddress((void**)&xhi,  g_xhi16);
    cudaGetSymbolAddress((void**)&Wemb, g_Wemb);
    cudaGetSymbolAddress((void**)&W4,   g_W4);
    cudaGetSymbolAddress((void**)&b4,   g_b4);
    cudaGetSymbolAddress((void**)&cnt,  g_cnt);

    cudaMemsetAsync(cnt, 0, (size_t)n * sizeof(int));

    // K1: convert | pad | direct-fill
    int CB = (n * HD / 4 + 255) / 256;
    int FB = (e / 4 + 255) / 256;
    prep_kernel<<<CB + 32 + FB, 256>>>(x, embW, Wl4, bl4, Wr4, ei, ew, n, e, CB);

    const int TG = 1480;
    // K2: embed transform (GEMM on xlo|xhi)
    transform_kernel<true, false, true, false><<<TG, 128>>>(
        xlo, xhi, Wemb, embB, Wemb + HD * HD, nullptr, 0, 0, hA16, n);

    int ggrid = (n + 7) / 8;
    gather_kernel<true><<<ggrid, 256>>>(hA16, mv16, n);
    transform_kernel<true, true, true, false><<<TG, 128>>>(
        mv16, hA16, Wl1, bl1, Wr1, nullptr, 0, 0, hB16, n);
    gather_kernel<true><<<ggrid, 256>>>(hB16, mv16, n);
    transform_kernel<true, true, true, false><<<TG, 128>>>(
        mv16, hB16, Wl2, bl2, Wr2, nullptr, 0, 0, hA16, n);
    gather_kernel<true><<<ggrid, 256>>>(hA16, mv16, n);
    transform_kernel<true, true, true, false><<<TG, 128>>>(
        mv16, hA16, Wl3, bl3, Wr3, nullptr, 0, 0, hB16, n);
    gather_kernel<false><<<ggrid, 256>>>(hB16, mv16, n);
    transform_kernel<false, true, false, true><<<TG, 128>>>(
        mv16, hB16, W4, b4, W4 + HD * HD, (float*)d_out, 18, 18, nullptr, n);
}